// round 5
// baseline (speedup 1.0000x reference)
#include <cuda_runtime.h>
#include <math.h>

#define T_LEN 256
#define BB 64
#define SENT_D 320
#define UU 512
#define G4 2048
#define HD 1024
#define NCTA_LSTM 128
#define ASTR 514            // padded A row stride (floats): conflict-free ty banks

// ---------------- packed f32x2 helpers (Blackwell FFMA2) ---------------------
__device__ __forceinline__ void fma2(unsigned long long& d,
                                     unsigned long long a, unsigned long long b) {
    asm("fma.rn.f32x2 %0, %1, %2, %0;" : "+l"(d) : "l"(a), "l"(b));
}
__device__ __forceinline__ unsigned long long dup2(float x) {
    unsigned long long r;
    asm("mov.b64 %0, {%1, %1};" : "=l"(r) : "f"(x));
    return r;
}
__device__ __forceinline__ float2 unpack2(unsigned long long v) {
    float2 r;
    asm("mov.b64 {%0, %1}, %2;" : "=f"(r.x), "=f"(r.y) : "l"(v));
    return r;
}

// ---------------- scratch (device globals; no allocs allowed) ----------------
__device__ float g_sent[T_LEN * BB * SENT_D];
__device__ float g_preF[(size_t)T_LEN * BB * G4];
__device__ float g_preB[(size_t)T_LEN * BB * G4];
__device__ float g_in2[(size_t)T_LEN * BB * 1024];
__device__ float g_fwd2[(size_t)T_LEN * BB * UU];
__device__ float g_back2[(size_t)T_LEN * BB * UU];

__device__ float g_Wx1f[SENT_D * G4], g_Wx1b[SENT_D * G4];
__device__ float g_Wh1f[UU * G4],     g_Wh1b[UU * G4];   // k-paired layout [256][4096]
__device__ float g_Wx2f[1024 * G4],   g_Wx2b[1024 * G4];
__device__ float g_Wh2f[UU * G4],     g_Wh2b[UU * G4];   // k-paired layout
__device__ float g_bv1f[G4], g_bv1b[G4], g_bv2f[G4], g_bv2b[G4];

__device__ float g_hFa[BB * UU], g_hFb[BB * UU];
__device__ float g_hBa[BB * UU], g_hBb[BB * UU];

__device__ float g_hi_s[BB * 8192];
__device__ float g_hi_l[BB * 6144];
__device__ float g_part_s[16 * BB * HD];
__device__ float g_part_l[12 * BB * HD];
__device__ float g_hs[BB * HD], g_hl[BB * HD];

__device__ unsigned g_bar_count = 0;
__device__ unsigned g_bar_gen = 0;

// ---------------- grid spin barrier (all 128 CTAs co-resident) ---------------
__device__ __forceinline__ void grid_barrier() {
    __syncthreads();
    if (threadIdx.x == 0) {
        __threadfence();
        unsigned gen = *((volatile unsigned*)&g_bar_gen);
        unsigned t = atomicAdd(&g_bar_count, 1);
        if (t == NCTA_LSTM - 1) {
            atomicExch(&g_bar_count, 0);
            __threadfence();
            atomicAdd(&g_bar_gen, 1);
        } else {
            while (*((volatile unsigned*)&g_bar_gen) == gen) {}
            __threadfence();
        }
    }
    __syncthreads();
}

// ---------------- weight packing ----------------------------------------------
// Wx: column n = u*4 + k (gate-interleaved).
// Wh: additionally k-pair-interleaved: Wh[(kd>>1)*4096 + n*2 + (kd&1)]
__global__ void pack_lstm(const float* __restrict__ W, const float* __restrict__ b,
                          float* __restrict__ Wx, float* __restrict__ Wh,
                          float* __restrict__ bv, int din) {
    int total = 4 * (din + UU) * UU;
    int stride = gridDim.x * blockDim.x;
    for (int idx = blockIdx.x * blockDim.x + threadIdx.x; idx < total; idx += stride) {
        int k = idx / ((din + UU) * UU);
        int rem = idx - k * ((din + UU) * UU);
        int d = rem / UU;
        int u = rem - d * UU;
        float v = W[idx];
        int n = u * 4 + k;
        if (d < din) {
            Wx[(size_t)d * G4 + n] = v;
        } else {
            int kd = d - din;
            Wh[(size_t)(kd >> 1) * 4096 + n * 2 + (kd & 1)] = v;
        }
    }
    for (int i = blockIdx.x * blockDim.x + threadIdx.x; i < G4; i += stride) {
        int k = i & 3, u = i >> 2;
        bv[i] = b[k * UU + u];
    }
}

// ---------------- embedding gather + concat ----------------------------------
__global__ void embed_kernel(const float* __restrict__ we, const float* __restrict__ te,
                             const int* __restrict__ wi, const int* __restrict__ ti) {
    int idx = blockIdx.x * blockDim.x + threadIdx.x;
    int tb = idx / SENT_D;
    int j = idx - tb * SENT_D;
    float v;
    if (j < 256) v = we[(size_t)wi[tb] * 256 + j];
    else         v = te[(size_t)ti[tb] * 64 + (j - 256)];
    g_sent[idx] = v;
}

// ---------------- LSTM h-state init ------------------------------------------
__global__ void init_states(const float* __restrict__ c0f, const float* __restrict__ c0b) {
    int idx = blockIdx.x * blockDim.x + threadIdx.x;   // B*U = 32768
    int u = idx & (UU - 1);
    g_hFa[idx] = tanhf(c0f[u]);
    g_hBa[idx] = tanhf(c0b[u]);
}

// ---------------- big SGEMM: C = A@B, 128x128 tiles, FFMA2 + prefetch --------
__global__ void __launch_bounds__(256) sgemm_128x128(
    const float* __restrict__ A, const float* __restrict__ B, float* __restrict__ C,
    int K, int lda, int ldb, int ldc) {
    __shared__ float As[16][132];   // As[kk][m]
    __shared__ float Bs[16][132];   // Bs[kk][n]
    int m0 = blockIdx.y * 128, n0 = blockIdx.x * 128;
    int tid = threadIdx.x;
    int tx = tid & 15, ty = tid >> 4;
    unsigned long long acc[4][8];
#pragma unroll
    for (int p = 0; p < 4; p++)
#pragma unroll
        for (int j = 0; j < 8; j++) acc[p][j] = 0ULL;

    int ar = tid >> 2, ac = (tid & 3) * 4;
    int bk = tid >> 5, bn = (tid & 31) * 4;

    // prefetch first tile
    float4 a0 = *(const float4*)(A + (size_t)(m0 + ar) * lda + ac);
    float4 a1 = *(const float4*)(A + (size_t)(m0 + ar + 64) * lda + ac);
    float4 b0 = *(const float4*)(B + (size_t)bk * ldb + n0 + bn);
    float4 b1 = *(const float4*)(B + (size_t)(bk + 8) * ldb + n0 + bn);

    for (int k0 = 0; k0 < K; k0 += 16) {
        __syncthreads();
        As[ac + 0][ar] = a0.x; As[ac + 1][ar] = a0.y; As[ac + 2][ar] = a0.z; As[ac + 3][ar] = a0.w;
        As[ac + 0][ar + 64] = a1.x; As[ac + 1][ar + 64] = a1.y; As[ac + 2][ar + 64] = a1.z; As[ac + 3][ar + 64] = a1.w;
        *(float4*)&Bs[bk][bn] = b0;
        *(float4*)&Bs[bk + 8][bn] = b1;
        __syncthreads();
        if (k0 + 16 < K) {   // prefetch next tile; latency overlaps compute below
            a0 = *(const float4*)(A + (size_t)(m0 + ar) * lda + k0 + 16 + ac);
            a1 = *(const float4*)(A + (size_t)(m0 + ar + 64) * lda + k0 + 16 + ac);
            b0 = *(const float4*)(B + (size_t)(k0 + 16 + bk) * ldb + n0 + bn);
            b1 = *(const float4*)(B + (size_t)(k0 + 24 + bk) * ldb + n0 + bn);
        }
#pragma unroll
        for (int kk = 0; kk < 16; kk++) {
            unsigned long long ap[4];
#pragma unroll
            for (int p = 0; p < 4; p++)
                ap[p] = *(const unsigned long long*)&As[kk][ty * 8 + 2 * p];
            float4 bv0 = *(float4*)&Bs[kk][tx * 8];
            float4 bv1 = *(float4*)&Bs[kk][tx * 8 + 4];
            unsigned long long bd[8] = {dup2(bv0.x), dup2(bv0.y), dup2(bv0.z), dup2(bv0.w),
                                        dup2(bv1.x), dup2(bv1.y), dup2(bv1.z), dup2(bv1.w)};
#pragma unroll
            for (int p = 0; p < 4; p++)
#pragma unroll
                for (int j = 0; j < 8; j++) fma2(acc[p][j], ap[p], bd[j]);
        }
    }
#pragma unroll
    for (int p = 0; p < 4; p++) {
        float v0[8], v1[8];
#pragma unroll
        for (int j = 0; j < 8; j++) {
            float2 t = unpack2(acc[p][j]);
            v0[j] = t.x; v1[j] = t.y;
        }
        float* c0 = C + (size_t)(m0 + ty * 8 + 2 * p) * ldc + n0 + tx * 8;
        float* c1 = c0 + ldc;
        *(float4*)c0 = make_float4(v0[0], v0[1], v0[2], v0[3]);
        *(float4*)(c0 + 4) = make_float4(v0[4], v0[5], v0[6], v0[7]);
        *(float4*)c1 = make_float4(v1[0], v1[1], v1[2], v1[3]);
        *(float4*)(c1 + 4) = make_float4(v1[4], v1[5], v1[6], v1[7]);
    }
}

// ---------------- persistent LSTM layer (both dirs, 256 steps, 1 launch) -----
// 128 CTAs x 128 threads, all co-resident. dir = blk>>6, nb = blk&63.
// Each CTA owns 8 units (32 gate columns). Wh slice resident in SMEM (64KB,
// k-paired). c state in registers. h exchanged via global + grid barrier.
__global__ void __launch_bounds__(128) lstm_layer(
    const float* __restrict__ preF, const float* __restrict__ preB,
    const float* __restrict__ WpF,  const float* __restrict__ WpB,
    const float* __restrict__ bvF,  const float* __restrict__ bvB,
    const float* __restrict__ c0F,  const float* __restrict__ c0B,
    float* __restrict__ outF, float* __restrict__ outB, int ostride) {
    extern __shared__ float sm[];
    float* Ws = sm;                 // [256][64] = 16384 floats
    float* As = sm + 16384;         // [64][ASTR] = 64*514 floats

    int blk = blockIdx.x;
    int dir = blk >> 6;
    int nb  = blk & 63;
    int n0  = nb * 32;

    const float* pre = dir ? preB : preF;
    const float* Wp  = dir ? WpB : WpF;
    const float* bv  = dir ? bvB : bvF;
    const float* c0  = dir ? c0B : c0F;
    float* outp = dir ? outB : outF;
    float* hbuf0 = dir ? g_hBa : g_hFa;
    float* hbuf1 = dir ? g_hBb : g_hFb;

    int tid = threadIdx.x;
    int tx = tid & 7, ty = tid >> 3;
    int u  = nb * 8 + tx;

    // load resident weight slice: rows 0..255, cols [n0*2, n0*2+64)
    for (int r = tid >> 2; r < 256; r += 32) {
        int seg = (tid & 3) * 16;
        const float4* src = (const float4*)(Wp + (size_t)r * 4096 + n0 * 2 + seg);
        float4* dst = (float4*)(Ws + r * 64 + seg);
        dst[0] = src[0]; dst[1] = src[1]; dst[2] = src[2]; dst[3] = src[3];
    }

    float4 bb4 = *(const float4*)(bv + n0 + tx * 4);
    float cinit = c0[u];
    float creg[4] = {cinit, cinit, cinit, cinit};

    int cb = tid >> 1, ch = tid & 1;           // copy assignment: b, half

    for (int s = 0; s < T_LEN; s++) {
        int t = dir ? (T_LEN - 1 - s) : s;
        const float* hin = (s & 1) ? hbuf1 : hbuf0;
        float* hout      = (s & 1) ? hbuf0 : hbuf1;

        // issue pre loads early (consumed after k-loop)
        float4 pv[4];
#pragma unroll
        for (int i = 0; i < 4; i++) {
            int b = ty * 4 + i;
            pv[i] = *(const float4*)(pre + ((size_t)t * BB + b) * G4 + n0 + tx * 4);
        }

        // stage hin -> As (padded rows)
        {
            const float4* src = (const float4*)(hin + cb * 512 + ch * 256);
            float* drow = As + cb * ASTR + ch * 256;
#pragma unroll
            for (int j = 0; j < 64; j++) {
                float4 v = src[j];
                *(float2*)(drow + j * 4)     = make_float2(v.x, v.y);
                *(float2*)(drow + j * 4 + 2) = make_float2(v.z, v.w);
            }
        }
        __syncthreads();

        // GEMM: acc[b][gate], FFMA2 packed over k-pairs (even/odd partial sums)
        unsigned long long acc[4][4];
#pragma unroll
        for (int i = 0; i < 4; i++)
#pragma unroll
            for (int j = 0; j < 4; j++) acc[i][j] = 0ULL;

#pragma unroll 8
        for (int kk2 = 0; kk2 < 256; kk2++) {
            unsigned long long ap[4];
#pragma unroll
            for (int i = 0; i < 4; i++)
                ap[i] = *(const unsigned long long*)(As + (ty * 4 + i) * ASTR + kk2 * 2);
            const unsigned long long* wrow =
                (const unsigned long long*)(Ws + kk2 * 64 + tx * 8);
            unsigned long long w0 = wrow[0], w1 = wrow[1], w2 = wrow[2], w3 = wrow[3];
#pragma unroll
            for (int i = 0; i < 4; i++) {
                fma2(acc[i][0], ap[i], w0);
                fma2(acc[i][1], ap[i], w1);
                fma2(acc[i][2], ap[i], w2);
                fma2(acc[i][3], ap[i], w3);
            }
        }

        // epilogue: fold even/odd, gates, state update
#pragma unroll
        for (int i = 0; i < 4; i++) {
            int b = ty * 4 + i;
            float2 e0 = unpack2(acc[i][0]);
            float2 e1 = unpack2(acc[i][1]);
            float2 e2 = unpack2(acc[i][2]);
            float2 e3 = unpack2(acc[i][3]);
            float gi = e0.x + e0.y + pv[i].x + bb4.x;
            float gf = e1.x + e1.y + pv[i].y + bb4.y;
            float go = e2.x + e2.y + pv[i].z + bb4.z;
            float gg = e3.x + e3.y + pv[i].w + bb4.w;
            float ig = 1.f / (1.f + expf(-gi));
            float fg = 1.f / (1.f + expf(-gf));
            float og = 1.f / (1.f + expf(-go));
            float gt = tanhf(gg);
            float c = fg * creg[i] + ig * gt;
            float h = og * tanhf(c);
            creg[i] = c;
            hout[b * UU + u] = h;
            outp[((size_t)t * BB + b) * ostride + u] = h;
        }

        grid_barrier();   // h visible to all CTAs; also guards As reuse
    }
}

// ---------------- span feature gather ----------------------------------------
__global__ void build_hi(const int* __restrict__ sl, const int* __restrict__ sr,
                         const int* __restrict__ ll, const int* __restrict__ lr) {
    int idx = blockIdx.x * blockDim.x + threadIdx.x;
    const int NS = BB * 4 * 2048;
    int b, s, c, le, ri;
    float* dst;
    if (idx < NS) {
        b = idx / (4 * 2048); int r = idx - b * (4 * 2048);
        s = r / 2048; c = r - s * 2048;
        le = sl[b * 4 + s]; ri = sr[b * 4 + s];
        dst = g_hi_s + (size_t)b * 8192 + s * 2048 + c;
    } else {
        int j = idx - NS;
        b = j / (3 * 2048); int r = j - b * (3 * 2048);
        s = r / 2048; c = r - s * 2048;
        le = ll[b * 3 + s]; ri = lr[b * 3 + s];
        dst = g_hi_l + (size_t)b * 6144 + s * 2048 + c;
    }
    float v;
    if (c < 512) {
        v = g_in2[((size_t)ri * BB + b) * 1024 + c] - g_in2[((size_t)(le - 1) * BB + b) * 1024 + c];
    } else if (c < 1024) {
        int u = c - 512;
        v = g_fwd2[((size_t)ri * BB + b) * UU + u] - g_fwd2[((size_t)(le - 1) * BB + b) * UU + u];
    } else if (c < 1536) {
        int u = c - 1024;
        v = g_in2[((size_t)le * BB + b) * 1024 + 512 + u] - g_in2[((size_t)(ri + 1) * BB + b) * 1024 + 512 + u];
    } else {
        int u = c - 1536;
        v = g_back2[((size_t)le * BB + b) * UU + u] - g_back2[((size_t)(ri + 1) * BB + b) * UU + u];
    }
    *dst = v;
}

// ---------------- span hidden GEMM: M=64, split-K into partial planes --------
__global__ void __launch_bounds__(256) span_gemm(
    const float* __restrict__ A, int lda, const float* __restrict__ B,
    float* __restrict__ Cpart) {
    __shared__ float AsT[16][68];
    __shared__ float Bs[16][68];
    int n0 = blockIdx.x * 64;
    int kbase = blockIdx.y * 512;
    int tid = threadIdx.x;
    int tx = tid & 15, ty = tid >> 4;
    float acc[4][4] = {{0}};
    int ab = tid >> 2, aseg = (tid & 3) * 4;
    int bkk = tid >> 4, bnn = (tid & 15) * 4;
    for (int k0 = kbase; k0 < kbase + 512; k0 += 16) {
        float4 av = *(const float4*)(A + (size_t)ab * lda + k0 + aseg);
        float4 wv = *(const float4*)(B + (size_t)(k0 + bkk) * HD + n0 + bnn);
        __syncthreads();
        AsT[aseg + 0][ab] = av.x; AsT[aseg + 1][ab] = av.y;
        AsT[aseg + 2][ab] = av.z; AsT[aseg + 3][ab] = av.w;
        *(float4*)&Bs[bkk][bnn] = wv;
        __syncthreads();
#pragma unroll
        for (int kk = 0; kk < 16; kk++) {
            float4 a = *(float4*)&AsT[kk][ty * 4];
            float4 w = *(float4*)&Bs[kk][tx * 4];
            float aa[4] = {a.x, a.y, a.z, a.w};
            float ww[4] = {w.x, w.y, w.z, w.w};
#pragma unroll
            for (int i = 0; i < 4; i++)
#pragma unroll
                for (int j = 0; j < 4; j++) acc[i][j] += aa[i] * ww[j];
        }
    }
#pragma unroll
    for (int i = 0; i < 4; i++) {
        int b = ty * 4 + i;
        float4 v = {acc[i][0], acc[i][1], acc[i][2], acc[i][3]};
        *(float4*)(Cpart + ((size_t)blockIdx.y * BB + b) * HD + n0 + tx * 4) = v;
    }
}

__global__ void reduce_relu(const float* __restrict__ part, int nch,
                            const float* __restrict__ bias, float* __restrict__ outh) {
    int idx = blockIdx.x * blockDim.x + threadIdx.x;
    int n = idx & (HD - 1);
    float s = bias[n];
    for (int ch = 0; ch < nch; ch++) s += part[(size_t)ch * BB * HD + idx];
    outh[idx] = fmaxf(s, 0.f);
}

// ---------------- output heads ------------------------------------------------
__global__ void out_heads(const float* __restrict__ soW, const float* __restrict__ sob,
                          const float* __restrict__ loW, const float* __restrict__ lob,
                          float* __restrict__ out) {
    __shared__ float s1[HD], s2[HD];
    int b = blockIdx.x, tid = threadIdx.x;
    for (int i = tid; i < HD; i += blockDim.x) {
        s1[i] = g_hs[b * HD + i];
        s2[i] = g_hl[b * HD + i];
    }
    __syncthreads();
    if (tid < 2) {
        float s = sob[tid];
        for (int k = 0; k < HD; k++) s += s1[k] * soW[k * 2 + tid];
        out[b * 2 + tid] = s;
    } else if (tid < 34) {
        int j = tid - 2;
        float s = lob[j];
        for (int k = 0; k < HD; k++) s += s2[k] * loW[k * 32 + j];
        out[128 + b * 32 + j] = s;
    }
}

// ---------------- host driver --------------------------------------------------
static float* sym(const void* symbol) {
    void* p = nullptr;
    cudaGetSymbolAddress(&p, symbol);
    return (float*)p;
}

extern "C" void kernel_launch(void* const* d_in, const int* in_sizes, int n_in,
                              void* d_out, int out_size) {
    const float* word_emb = (const float*)d_in[0];
    const float* tag_emb  = (const float*)d_in[1];
    const float* l1f_W = (const float*)d_in[2];
    const float* l1f_b = (const float*)d_in[3];
    const float* l1f_c0 = (const float*)d_in[4];
    const float* l1b_W = (const float*)d_in[5];
    const float* l1b_b = (const float*)d_in[6];
    const float* l1b_c0 = (const float*)d_in[7];
    const float* l2f_W = (const float*)d_in[8];
    const float* l2f_b = (const float*)d_in[9];
    const float* l2f_c0 = (const float*)d_in[10];
    const float* l2b_W = (const float*)d_in[11];
    const float* l2b_b = (const float*)d_in[12];
    const float* l2b_c0 = (const float*)d_in[13];
    const float* sh_W = (const float*)d_in[14];
    const float* sh_b = (const float*)d_in[15];
    const float* so_W = (const float*)d_in[16];
    const float* so_b = (const float*)d_in[17];
    const float* lh_W = (const float*)d_in[18];
    const float* lh_b = (const float*)d_in[19];
    const float* lo_W = (const float*)d_in[20];
    const float* lo_b = (const float*)d_in[21];
    const int* word_inds = (const int*)d_in[22];
    const int* tag_inds  = (const int*)d_in[23];
    const int* s_lefts  = (const int*)d_in[24];
    const int* s_rights = (const int*)d_in[25];
    const int* l_lefts  = (const int*)d_in[26];
    const int* l_rights = (const int*)d_in[27];
    float* out = (float*)d_out;

    float* p_sent  = sym(g_sent);
    float* p_preF  = sym(g_preF);
    float* p_preB  = sym(g_preB);
    float* p_in2   = sym(g_in2);
    float* p_fwd2  = sym(g_fwd2);
    float* p_back2 = sym(g_back2);
    float* p_Wx1f = sym(g_Wx1f); float* p_Wx1b = sym(g_Wx1b);
    float* p_Wh1f = sym(g_Wh1f); float* p_Wh1b = sym(g_Wh1b);
    float* p_Wx2f = sym(g_Wx2f); float* p_Wx2b = sym(g_Wx2b);
    float* p_Wh2f = sym(g_Wh2f); float* p_Wh2b = sym(g_Wh2b);
    float* p_bv1f = sym(g_bv1f); float* p_bv1b = sym(g_bv1b);
    float* p_bv2f = sym(g_bv2f); float* p_bv2b = sym(g_bv2b);
    float* p_hi_s = sym(g_hi_s); float* p_hi_l = sym(g_hi_l);
    float* p_part_s = sym(g_part_s); float* p_part_l = sym(g_part_l);
    float* p_hs = sym(g_hs); float* p_hl = sym(g_hl);

    static int smem_set = 0;
    const int LSTM_SMEM = (16384 + 64 * ASTR) * 4;   // 197120 B
    if (!smem_set) {
        cudaFuncSetAttribute(lstm_layer, cudaFuncAttributeMaxDynamicSharedMemorySize,
                             LSTM_SMEM);
        smem_set = 1;
    }

    // 1) pack weights
    pack_lstm<<<2048, 256>>>(l1f_W, l1f_b, p_Wx1f, p_Wh1f, p_bv1f, SENT_D);
    pack_lstm<<<2048, 256>>>(l1b_W, l1b_b, p_Wx1b, p_Wh1b, p_bv1b, SENT_D);
    pack_lstm<<<4096, 256>>>(l2f_W, l2f_b, p_Wx2f, p_Wh2f, p_bv2f, 1024);
    pack_lstm<<<4096, 256>>>(l2b_W, l2b_b, p_Wx2b, p_Wh2b, p_bv2b, 1024);

    // 2) embeddings
    embed_kernel<<<(T_LEN * BB * SENT_D) / 256, 256>>>(word_emb, tag_emb, word_inds, tag_inds);

    // 3) layer-1 input projections (16384 x 320 x 2048)
    dim3 gpre(G4 / 128, (T_LEN * BB) / 128);
    sgemm_128x128<<<gpre, 256>>>(p_sent, p_Wx1f, p_preF, SENT_D, SENT_D, G4, G4);
    sgemm_128x128<<<gpre, 256>>>(p_sent, p_Wx1b, p_preB, SENT_D, SENT_D, G4, G4);

    // 4) layer-1 recurrence: ONE persistent launch
    init_states<<<(BB * UU) / 256, 256>>>(l1f_c0, l1b_c0);
    lstm_layer<<<NCTA_LSTM, 128, LSTM_SMEM>>>(
        p_preF, p_preB, p_Wh1f, p_Wh1b, p_bv1f, p_bv1b, l1f_c0, l1b_c0,
        p_in2, p_in2 + 512, 1024);

    // 5) layer-2 input projections (16384 x 1024 x 2048)
    sgemm_128x128<<<gpre, 256>>>(p_in2, p_Wx2f, p_preF, 1024, 1024, G4, G4);
    sgemm_128x128<<<gpre, 256>>>(p_in2, p_Wx2b, p_preB, 1024, 1024, G4, G4);

    // 6) layer-2 recurrence
    init_states<<<(BB * UU) / 256, 256>>>(l2f_c0, l2b_c0);
    lstm_layer<<<NCTA_LSTM, 128, LSTM_SMEM>>>(
        p_preF, p_preB, p_Wh2f, p_Wh2b, p_bv2f, p_bv2b, l2f_c0, l2b_c0,
        p_fwd2, p_back2, UU);

    // 7) span features
    build_hi<<<(BB * 7 * 2048) / 256, 256>>>(s_lefts, s_rights, l_lefts, l_rights);

    // 8) span hidden layers
    span_gemm<<<dim3(HD / 64, 16), 256>>>(p_hi_s, 8192, sh_W, p_part_s);
    span_gemm<<<dim3(HD / 64, 12), 256>>>(p_hi_l, 6144, lh_W, p_part_l);
    reduce_relu<<<(BB * HD) / 256, 256>>>(p_part_s, 16, sh_b, p_hs);
    reduce_relu<<<(BB * HD) / 256, 256>>>(p_part_l, 12, lh_b, p_hl);

    // 9) output heads
    out_heads<<<BB, 128>>>(so_W, so_b, lo_W, lo_b, out);
}

// round 6
// speedup vs baseline: 1.0316x; 1.0316x over previous
#include <cuda_runtime.h>
#include <math.h>

#define T_LEN 256
#define BB 64
#define SENT_D 320
#define UU 512
#define G4 2048
#define HD 1024

typedef unsigned long long ull;

// ---------------- packed f32x2 helpers (Blackwell FFMA2) ---------------------
__device__ __forceinline__ void fma2(ull& d, ull a, ull b) {
    asm("fma.rn.f32x2 %0, %1, %2, %0;" : "+l"(d) : "l"(a), "l"(b));
}
__device__ __forceinline__ ull dup2(float x) {
    ull r;
    asm("mov.b64 %0, {%1, %1};" : "=l"(r) : "f"(x));
    return r;
}
__device__ __forceinline__ float2 unpack2(ull v) {
    float2 r;
    asm("mov.b64 {%0, %1}, %2;" : "=f"(r.x), "=f"(r.y) : "l"(v));
    return r;
}

// ---------------- scratch (device globals; no allocs allowed) ----------------
__device__ float g_sent[T_LEN * BB * SENT_D];
__device__ float g_preF[(size_t)T_LEN * BB * G4];
__device__ float g_preB[(size_t)T_LEN * BB * G4];
__device__ float g_in2[(size_t)T_LEN * BB * 1024];
__device__ float g_fwd2[(size_t)T_LEN * BB * UU];
__device__ float g_back2[(size_t)T_LEN * BB * UU];

__device__ float g_Wx1f[SENT_D * G4], g_Wx1b[SENT_D * G4];
__device__ float g_Wh1f[UU * G4],     g_Wh1b[UU * G4];   // k-paired [256][4096]
__device__ float g_Wx2f[1024 * G4],   g_Wx2b[1024 * G4];
__device__ float g_Wh2f[UU * G4],     g_Wh2b[UU * G4];   // k-paired
__device__ float g_bv1f[G4], g_bv1b[G4], g_bv2f[G4], g_bv2b[G4];

__device__ float g_hFa[BB * UU], g_hFb[BB * UU];
__device__ float g_hBa[BB * UU], g_hBb[BB * UU];
__device__ float g_cF[BB * UU],  g_cB[BB * UU];

__device__ float g_hi_s[BB * 8192];
__device__ float g_hi_l[BB * 6144];
__device__ float g_part_s[16 * BB * HD];
__device__ float g_part_l[12 * BB * HD];
__device__ float g_hs[BB * HD], g_hl[BB * HD];

// ---------------- weight packing ----------------------------------------------
// Wx: column n = u*4 + k (gate-interleaved).
// Wh: additionally k-pair-interleaved: Wh[(kd>>1)*4096 + n*2 + (kd&1)]
__global__ void pack_lstm(const float* __restrict__ W, const float* __restrict__ b,
                          float* __restrict__ Wx, float* __restrict__ Wh,
                          float* __restrict__ bv, int din) {
    int total = 4 * (din + UU) * UU;
    int stride = gridDim.x * blockDim.x;
    for (int idx = blockIdx.x * blockDim.x + threadIdx.x; idx < total; idx += stride) {
        int k = idx / ((din + UU) * UU);
        int rem = idx - k * ((din + UU) * UU);
        int d = rem / UU;
        int u = rem - d * UU;
        float v = W[idx];
        int n = u * 4 + k;
        if (d < din) {
            Wx[(size_t)d * G4 + n] = v;
        } else {
            int kd = d - din;
            Wh[(size_t)(kd >> 1) * 4096 + n * 2 + (kd & 1)] = v;
        }
    }
    for (int i = blockIdx.x * blockDim.x + threadIdx.x; i < G4; i += stride) {
        int k = i & 3, u = i >> 2;
        bv[i] = b[k * UU + u];
    }
}

// ---------------- embedding gather + concat ----------------------------------
__global__ void embed_kernel(const float* __restrict__ we, const float* __restrict__ te,
                             const int* __restrict__ wi, const int* __restrict__ ti) {
    int idx = blockIdx.x * blockDim.x + threadIdx.x;
    int tb = idx / SENT_D;
    int j = idx - tb * SENT_D;
    float v;
    if (j < 256) v = we[(size_t)wi[tb] * 256 + j];
    else         v = te[(size_t)ti[tb] * 64 + (j - 256)];
    g_sent[idx] = v;
}

// ---------------- LSTM state init --------------------------------------------
__global__ void init_states(const float* __restrict__ c0f, const float* __restrict__ c0b) {
    int idx = blockIdx.x * blockDim.x + threadIdx.x;   // B*U = 32768
    int u = idx & (UU - 1);
    float cf = c0f[u], cb = c0b[u];
    g_cF[idx] = cf;  g_hFa[idx] = tanhf(cf);
    g_cB[idx] = cb;  g_hBa[idx] = tanhf(cb);
}

// ---------------- big SGEMM: C = A@B, 128x128 tiles, FFMA2 + prefetch --------
__global__ void __launch_bounds__(256) sgemm_128x128(
    const float* __restrict__ A, const float* __restrict__ B, float* __restrict__ C,
    int K, int lda, int ldb, int ldc) {
    __shared__ float As[16][132];   // As[kk][m]
    __shared__ float Bs[16][132];   // Bs[kk][n]
    int m0 = blockIdx.y * 128, n0 = blockIdx.x * 128;
    int tid = threadIdx.x;
    int tx = tid & 15, ty = tid >> 4;
    ull acc[4][8];
#pragma unroll
    for (int p = 0; p < 4; p++)
#pragma unroll
        for (int j = 0; j < 8; j++) acc[p][j] = 0ULL;

    int ar = tid >> 2, ac = (tid & 3) * 4;
    int bk = tid >> 5, bn = (tid & 31) * 4;

    float4 a0 = *(const float4*)(A + (size_t)(m0 + ar) * lda + ac);
    float4 a1 = *(const float4*)(A + (size_t)(m0 + ar + 64) * lda + ac);
    float4 b0 = *(const float4*)(B + (size_t)bk * ldb + n0 + bn);
    float4 b1 = *(const float4*)(B + (size_t)(bk + 8) * ldb + n0 + bn);

    for (int k0 = 0; k0 < K; k0 += 16) {
        __syncthreads();
        As[ac + 0][ar] = a0.x; As[ac + 1][ar] = a0.y; As[ac + 2][ar] = a0.z; As[ac + 3][ar] = a0.w;
        As[ac + 0][ar + 64] = a1.x; As[ac + 1][ar + 64] = a1.y; As[ac + 2][ar + 64] = a1.z; As[ac + 3][ar + 64] = a1.w;
        *(float4*)&Bs[bk][bn] = b0;
        *(float4*)&Bs[bk + 8][bn] = b1;
        __syncthreads();
        if (k0 + 16 < K) {
            a0 = *(const float4*)(A + (size_t)(m0 + ar) * lda + k0 + 16 + ac);
            a1 = *(const float4*)(A + (size_t)(m0 + ar + 64) * lda + k0 + 16 + ac);
            b0 = *(const float4*)(B + (size_t)(k0 + 16 + bk) * ldb + n0 + bn);
            b1 = *(const float4*)(B + (size_t)(k0 + 24 + bk) * ldb + n0 + bn);
        }
#pragma unroll
        for (int kk = 0; kk < 16; kk++) {
            ull ap[4];
#pragma unroll
            for (int p = 0; p < 4; p++)
                ap[p] = *(const ull*)&As[kk][ty * 8 + 2 * p];
            float4 bv0 = *(float4*)&Bs[kk][tx * 8];
            float4 bv1 = *(float4*)&Bs[kk][tx * 8 + 4];
            ull bd[8] = {dup2(bv0.x), dup2(bv0.y), dup2(bv0.z), dup2(bv0.w),
                         dup2(bv1.x), dup2(bv1.y), dup2(bv1.z), dup2(bv1.w)};
#pragma unroll
            for (int p = 0; p < 4; p++)
#pragma unroll
                for (int j = 0; j < 8; j++) fma2(acc[p][j], ap[p], bd[j]);
        }
    }
#pragma unroll
    for (int p = 0; p < 4; p++) {
        float v0[8], v1[8];
#pragma unroll
        for (int j = 0; j < 8; j++) {
            float2 t = unpack2(acc[p][j]);
            v0[j] = t.x; v1[j] = t.y;
        }
        float* c0 = C + (size_t)(m0 + ty * 8 + 2 * p) * ldc + n0 + tx * 8;
        float* c1 = c0 + ldc;
        *(float4*)c0 = make_float4(v0[0], v0[1], v0[2], v0[3]);
        *(float4*)(c0 + 4) = make_float4(v0[4], v0[5], v0[6], v0[7]);
        *(float4*)c1 = make_float4(v1[0], v1[1], v1[2], v1[3]);
        *(float4*)(c1 + 4) = make_float4(v1[4], v1[5], v1[6], v1[7]);
    }
}

// ---------------- one recurrent step, both dirs, 256 threads -----------------
// grid = 128 CTAs: blk>>6 = dir, blk&63 = 32-wide gate tile (8 units).
// Thread tile: 2 batch rows x 4 gates (1 unit); FFMA2 packs k-pairs.
// Double-buffered 32-k staging blocks, 1 barrier per block, reg prefetch.
#define ASTR44 44
__global__ void __launch_bounds__(256) lstm_step(
    const float* __restrict__ preF, const float* __restrict__ preB,
    const float* __restrict__ WpF,  const float* __restrict__ WpB,
    const float* __restrict__ bvF,  const float* __restrict__ bvB,
    const float* __restrict__ hinF, float* __restrict__ houtF,
    const float* __restrict__ hinB, float* __restrict__ houtB,
    float* __restrict__ outF, float* __restrict__ outB,
    int ostride, int tF, int tB) {
    __shared__ __align__(16) float As[2][64 * ASTR44];  // [buf][b*44 + k(0..31)]
    __shared__ __align__(16) float Bs[2][16 * 64];      // [buf][kk2*64 + c]

    int blk = blockIdx.x;
    int dir = blk >> 6;
    int nb  = blk & 63;
    int n0  = nb * 32;

    const float* pre = dir ? preB : preF;
    const float* Wp  = dir ? WpB : WpF;
    const float* bv  = dir ? bvB : bvF;
    const float* hin = dir ? hinB : hinF;
    float* hout = dir ? houtB : houtF;
    float* cst  = dir ? g_cB : g_cF;
    float* outp = dir ? outB : outF;
    int t = dir ? tB : tF;

    int tid = threadIdx.x;
    int tx = tid & 7, ty = tid >> 3;          // tx: unit, ty: b-pair (0..31)
    int b0 = ty * 2, b1 = b0 + 1;
    int u = nb * 8 + tx;

    // early independent loads (L2 latency hides under the k-loop)
    float4 pv0 = *(const float4*)(pre + ((size_t)t * BB + b0) * G4 + n0 + tx * 4);
    float4 pv1 = *(const float4*)(pre + ((size_t)t * BB + b1) * G4 + n0 + tx * 4);
    float4 bb4 = *(const float4*)(bv + n0 + tx * 4);
    float cv0 = cst[b0 * UU + u];
    float cv1 = cst[b1 * UU + u];

    // staging assignments
    int sb = tid >> 2, sseg = (tid & 3) * 4;  // A: row sb, 8 floats (2 float4)
    int wr = tid >> 4, wc = (tid & 15) * 4;   // W: 16 kpair-rows x 64

    // prologue: stage block k0=0
    {
        float4 a40 = *(const float4*)(hin + sb * UU + sseg);
        float4 a41 = *(const float4*)(hin + sb * UU + sseg + 16);
        float4 w4  = *(const float4*)(Wp + (size_t)wr * 4096 + n0 * 2 + wc);
        *(float4*)&As[0][sb * ASTR44 + sseg]      = a40;
        *(float4*)&As[0][sb * ASTR44 + sseg + 16] = a41;
        *(float4*)&Bs[0][wr * 64 + wc] = w4;
    }
    __syncthreads();

    ull acc[2][4];
#pragma unroll
    for (int i = 0; i < 2; i++)
#pragma unroll
        for (int j = 0; j < 4; j++) acc[i][j] = 0ULL;

    int p = 0;
    for (int k0 = 0; k0 < UU; k0 += 32, p ^= 1) {
        int kn = k0 + 32;
        float4 na0, na1, nw;
        bool more = (kn < UU);
        if (more) {
            na0 = *(const float4*)(hin + sb * UU + kn + sseg);
            na1 = *(const float4*)(hin + sb * UU + kn + sseg + 16);
            nw  = *(const float4*)(Wp + (size_t)((kn >> 1) + wr) * 4096 + n0 * 2 + wc);
        }
        const float* Ap = As[p];
        const float* Bp = Bs[p];
#pragma unroll
        for (int kk2 = 0; kk2 < 16; kk2++) {
            ull a0 = *(const ull*)(Ap + b0 * ASTR44 + kk2 * 2);
            ull a1 = *(const ull*)(Ap + b1 * ASTR44 + kk2 * 2);
            ulonglong2 wA = *(const ulonglong2*)(Bp + kk2 * 64 + tx * 8);
            ulonglong2 wB = *(const ulonglong2*)(Bp + kk2 * 64 + tx * 8 + 4);
            fma2(acc[0][0], a0, wA.x); fma2(acc[0][1], a0, wA.y);
            fma2(acc[0][2], a0, wB.x); fma2(acc[0][3], a0, wB.y);
            fma2(acc[1][0], a1, wA.x); fma2(acc[1][1], a1, wA.y);
            fma2(acc[1][2], a1, wB.x); fma2(acc[1][3], a1, wB.y);
        }
        if (more) {
            *(float4*)&As[p ^ 1][sb * ASTR44 + sseg]      = na0;
            *(float4*)&As[p ^ 1][sb * ASTR44 + sseg + 16] = na1;
            *(float4*)&Bs[p ^ 1][wr * 64 + wc] = nw;
        }
        __syncthreads();
    }

    // epilogue: fold k-even/odd partials, gates, state update
#pragma unroll
    for (int i = 0; i < 2; i++) {
        int b = (i == 0) ? b0 : b1;
        float4 pv = (i == 0) ? pv0 : pv1;
        float cv  = (i == 0) ? cv0 : cv1;
        float2 e0 = unpack2(acc[i][0]);
        float2 e1 = unpack2(acc[i][1]);
        float2 e2 = unpack2(acc[i][2]);
        float2 e3 = unpack2(acc[i][3]);
        float gi = e0.x + e0.y + pv.x + bb4.x;
        float gf = e1.x + e1.y + pv.y + bb4.y;
        float go = e2.x + e2.y + pv.z + bb4.z;
        float gg = e3.x + e3.y + pv.w + bb4.w;
        float ig = 1.f / (1.f + expf(-gi));
        float fg = 1.f / (1.f + expf(-gf));
        float og = 1.f / (1.f + expf(-go));
        float gt = tanhf(gg);
        float c = fg * cv + ig * gt;
        float h = og * tanhf(c);
        cst[b * UU + u] = c;
        hout[b * UU + u] = h;
        outp[((size_t)t * BB + b) * ostride + u] = h;
    }
}

// ---------------- span feature gather ----------------------------------------
__global__ void build_hi(const int* __restrict__ sl, const int* __restrict__ sr,
                         const int* __restrict__ ll, const int* __restrict__ lr) {
    int idx = blockIdx.x * blockDim.x + threadIdx.x;
    const int NS = BB * 4 * 2048;
    int b, s, c, le, ri;
    float* dst;
    if (idx < NS) {
        b = idx / (4 * 2048); int r = idx - b * (4 * 2048);
        s = r / 2048; c = r - s * 2048;
        le = sl[b * 4 + s]; ri = sr[b * 4 + s];
        dst = g_hi_s + (size_t)b * 8192 + s * 2048 + c;
    } else {
        int j = idx - NS;
        b = j / (3 * 2048); int r = j - b * (3 * 2048);
        s = r / 2048; c = r - s * 2048;
        le = ll[b * 3 + s]; ri = lr[b * 3 + s];
        dst = g_hi_l + (size_t)b * 6144 + s * 2048 + c;
    }
    float v;
    if (c < 512) {
        v = g_in2[((size_t)ri * BB + b) * 1024 + c] - g_in2[((size_t)(le - 1) * BB + b) * 1024 + c];
    } else if (c < 1024) {
        int u = c - 512;
        v = g_fwd2[((size_t)ri * BB + b) * UU + u] - g_fwd2[((size_t)(le - 1) * BB + b) * UU + u];
    } else if (c < 1536) {
        int u = c - 1024;
        v = g_in2[((size_t)le * BB + b) * 1024 + 512 + u] - g_in2[((size_t)(ri + 1) * BB + b) * 1024 + 512 + u];
    } else {
        int u = c - 1536;
        v = g_back2[((size_t)le * BB + b) * UU + u] - g_back2[((size_t)(ri + 1) * BB + b) * UU + u];
    }
    *dst = v;
}

// ---------------- span hidden GEMM: M=64, split-K into partial planes --------
__global__ void __launch_bounds__(256) span_gemm(
    const float* __restrict__ A, int lda, const float* __restrict__ B,
    float* __restrict__ Cpart) {
    __shared__ float AsT[16][68];
    __shared__ float Bs[16][68];
    int n0 = blockIdx.x * 64;
    int kbase = blockIdx.y * 512;
    int tid = threadIdx.x;
    int tx = tid & 15, ty = tid >> 4;
    float acc[4][4] = {{0}};
    int ab = tid >> 2, aseg = (tid & 3) * 4;
    int bkk = tid >> 4, bnn = (tid & 15) * 4;
    for (int k0 = kbase; k0 < kbase + 512; k0 += 16) {
        float4 av = *(const float4*)(A + (size_t)ab * lda + k0 + aseg);
        float4 wv = *(const float4*)(B + (size_t)(k0 + bkk) * HD + n0 + bnn);
        __syncthreads();
        AsT[aseg + 0][ab] = av.x; AsT[aseg + 1][ab] = av.y;
        AsT[aseg + 2][ab] = av.z; AsT[aseg + 3][ab] = av.w;
        *(float4*)&Bs[bkk][bnn] = wv;
        __syncthreads();
#pragma unroll
        for (int kk = 0; kk < 16; kk++) {
            float4 a = *(float4*)&AsT[kk][ty * 4];
            float4 w = *(float4*)&Bs[kk][tx * 4];
            float aa[4] = {a.x, a.y, a.z, a.w};
            float ww[4] = {w.x, w.y, w.z, w.w};
#pragma unroll
            for (int i = 0; i < 4; i++)
#pragma unroll
                for (int j = 0; j < 4; j++) acc[i][j] += aa[i] * ww[j];
        }
    }
#pragma unroll
    for (int i = 0; i < 4; i++) {
        int b = ty * 4 + i;
        float4 v = {acc[i][0], acc[i][1], acc[i][2], acc[i][3]};
        *(float4*)(Cpart + ((size_t)blockIdx.y * BB + b) * HD + n0 + tx * 4) = v;
    }
}

__global__ void reduce_relu(const float* __restrict__ part, int nch,
                            const float* __restrict__ bias, float* __restrict__ outh) {
    int idx = blockIdx.x * blockDim.x + threadIdx.x;
    int n = idx & (HD - 1);
    float s = bias[n];
    for (int ch = 0; ch < nch; ch++) s += part[(size_t)ch * BB * HD + idx];
    outh[idx] = fmaxf(s, 0.f);
}

// ---------------- output heads ------------------------------------------------
__global__ void out_heads(const float* __restrict__ soW, const float* __restrict__ sob,
                          const float* __restrict__ loW, const float* __restrict__ lob,
                          float* __restrict__ out) {
    __shared__ float s1[HD], s2[HD];
    int b = blockIdx.x, tid = threadIdx.x;
    for (int i = tid; i < HD; i += blockDim.x) {
        s1[i] = g_hs[b * HD + i];
        s2[i] = g_hl[b * HD + i];
    }
    __syncthreads();
    if (tid < 2) {
        float s = sob[tid];
        for (int k = 0; k < HD; k++) s += s1[k] * soW[k * 2 + tid];
        out[b * 2 + tid] = s;
    } else if (tid < 34) {
        int j = tid - 2;
        float s = lob[j];
        for (int k = 0; k < HD; k++) s += s2[k] * loW[k * 32 + j];
        out[128 + b * 32 + j] = s;
    }
}

// ---------------- host driver --------------------------------------------------
static float* sym(const void* symbol) {
    void* p = nullptr;
    cudaGetSymbolAddress(&p, symbol);
    return (float*)p;
}

extern "C" void kernel_launch(void* const* d_in, const int* in_sizes, int n_in,
                              void* d_out, int out_size) {
    const float* word_emb = (const float*)d_in[0];
    const float* tag_emb  = (const float*)d_in[1];
    const float* l1f_W = (const float*)d_in[2];
    const float* l1f_b = (const float*)d_in[3];
    const float* l1f_c0 = (const float*)d_in[4];
    const float* l1b_W = (const float*)d_in[5];
    const float* l1b_b = (const float*)d_in[6];
    const float* l1b_c0 = (const float*)d_in[7];
    const float* l2f_W = (const float*)d_in[8];
    const float* l2f_b = (const float*)d_in[9];
    const float* l2f_c0 = (const float*)d_in[10];
    const float* l2b_W = (const float*)d_in[11];
    const float* l2b_b = (const float*)d_in[12];
    const float* l2b_c0 = (const float*)d_in[13];
    const float* sh_W = (const float*)d_in[14];
    const float* sh_b = (const float*)d_in[15];
    const float* so_W = (const float*)d_in[16];
    const float* so_b = (const float*)d_in[17];
    const float* lh_W = (const float*)d_in[18];
    const float* lh_b = (const float*)d_in[19];
    const float* lo_W = (const float*)d_in[20];
    const float* lo_b = (const float*)d_in[21];
    const int* word_inds = (const int*)d_in[22];
    const int* tag_inds  = (const int*)d_in[23];
    const int* s_lefts  = (const int*)d_in[24];
    const int* s_rights = (const int*)d_in[25];
    const int* l_lefts  = (const int*)d_in[26];
    const int* l_rights = (const int*)d_in[27];
    float* out = (float*)d_out;

    float* p_sent  = sym(g_sent);
    float* p_preF  = sym(g_preF);
    float* p_preB  = sym(g_preB);
    float* p_in2   = sym(g_in2);
    float* p_fwd2  = sym(g_fwd2);
    float* p_back2 = sym(g_back2);
    float* p_Wx1f = sym(g_Wx1f); float* p_Wx1b = sym(g_Wx1b);
    float* p_Wh1f = sym(g_Wh1f); float* p_Wh1b = sym(g_Wh1b);
    float* p_Wx2f = sym(g_Wx2f); float* p_Wx2b = sym(g_Wx2b);
    float* p_Wh2f = sym(g_Wh2f); float* p_Wh2b = sym(g_Wh2b);
    float* p_bv1f = sym(g_bv1f); float* p_bv1b = sym(g_bv1b);
    float* p_bv2f = sym(g_bv2f); float* p_bv2b = sym(g_bv2b);
    float* p_hFa = sym(g_hFa); float* p_hFb = sym(g_hFb);
    float* p_hBa = sym(g_hBa); float* p_hBb = sym(g_hBb);
    float* p_hi_s = sym(g_hi_s); float* p_hi_l = sym(g_hi_l);
    float* p_part_s = sym(g_part_s); float* p_part_l = sym(g_part_l);
    float* p_hs = sym(g_hs); float* p_hl = sym(g_hl);

    // 1) pack weights
    pack_lstm<<<2048, 256>>>(l1f_W, l1f_b, p_Wx1f, p_Wh1f, p_bv1f, SENT_D);
    pack_lstm<<<2048, 256>>>(l1b_W, l1b_b, p_Wx1b, p_Wh1b, p_bv1b, SENT_D);
    pack_lstm<<<4096, 256>>>(l2f_W, l2f_b, p_Wx2f, p_Wh2f, p_bv2f, 1024);
    pack_lstm<<<4096, 256>>>(l2b_W, l2b_b, p_Wx2b, p_Wh2b, p_bv2b, 1024);

    // 2) embeddings
    embed_kernel<<<(T_LEN * BB * SENT_D) / 256, 256>>>(word_emb, tag_emb, word_inds, tag_inds);

    // 3) layer-1 input projections (16384 x 320 x 2048)
    dim3 gpre(G4 / 128, (T_LEN * BB) / 128);
    sgemm_128x128<<<gpre, 256>>>(p_sent, p_Wx1f, p_preF, SENT_D, SENT_D, G4, G4);
    sgemm_128x128<<<gpre, 256>>>(p_sent, p_Wx1b, p_preB, SENT_D, SENT_D, G4, G4);

    // 4) layer-1 recurrence
    init_states<<<(BB * UU) / 256, 256>>>(l1f_c0, l1b_c0);
    for (int s = 0; s < T_LEN; s++) {
        const float* hinF = (s & 1) ? p_hFb : p_hFa;
        float* houtF      = (s & 1) ? p_hFa : p_hFb;
        const float* hinB = (s & 1) ? p_hBb : p_hBa;
        float* houtB      = (s & 1) ? p_hBa : p_hBb;
        lstm_step<<<128, 256>>>(p_preF, p_preB, p_Wh1f, p_Wh1b, p_bv1f, p_bv1b,
                                hinF, houtF, hinB, houtB,
                                p_in2, p_in2 + 512, 1024, s, T_LEN - 1 - s);
    }

    // 5) layer-2 input projections (16384 x 1024 x 2048)
    sgemm_128x128<<<gpre, 256>>>(p_in2, p_Wx2f, p_preF, 1024, 1024, G4, G4);
    sgemm_128x128<<<gpre, 256>>>(p_in2, p_Wx2b, p_preB, 1024, 1024, G4, G4);

    // 6) layer-2 recurrence
    init_states<<<(BB * UU) / 256, 256>>>(l2f_c0, l2b_c0);
    for (int s = 0; s < T_LEN; s++) {
        const float* hinF = (s & 1) ? p_hFb : p_hFa;
        float* houtF      = (s & 1) ? p_hFa : p_hFb;
        const float* hinB = (s & 1) ? p_hBb : p_hBa;
        float* houtB      = (s & 1) ? p_hBa : p_hBb;
        lstm_step<<<128, 256>>>(p_preF, p_preB, p_Wh2f, p_Wh2b, p_bv2f, p_bv2b,
                                hinF, houtF, hinB, houtB,
                                p_fwd2, p_back2, UU, s, T_LEN - 1 - s);
    }

    // 7) span features
    build_hi<<<(BB * 7 * 2048) / 256, 256>>>(s_lefts, s_rights, l_lefts, l_rights);

    // 8) span hidden layers
    span_gemm<<<dim3(HD / 64, 16), 256>>>(p_hi_s, 8192, sh_W, p_part_s);
    span_gemm<<<dim3(HD / 64, 12), 256>>>(p_hi_l, 6144, lh_W, p_part_l);
    reduce_relu<<<(BB * HD) / 256, 256>>>(p_part_s, 16, sh_b, p_hs);
    reduce_relu<<<(BB * HD) / 256, 256>>>(p_part_l, 12, lh_b, p_hl);

    // 9) output heads
    out_heads<<<BB, 128>>>(so_W, so_b, lo_W, lo_b, out);
}

// round 7
// speedup vs baseline: 1.0748x; 1.0418x over previous
#include <cuda_runtime.h>
#include <math.h>

#define T_LEN 256
#define BB 64
#define SENT_D 320
#define UU 512
#define G4 2048
#define HD 1024

typedef unsigned long long ull;

// ---------------- packed f32x2 helpers (Blackwell FFMA2) ---------------------
__device__ __forceinline__ void fma2(ull& d, ull a, ull b) {
    asm("fma.rn.f32x2 %0, %1, %2, %0;" : "+l"(d) : "l"(a), "l"(b));
}
__device__ __forceinline__ ull dup2(float x) {
    ull r;
    asm("mov.b64 %0, {%1, %1};" : "=l"(r) : "f"(x));
    return r;
}
__device__ __forceinline__ float2 unpack2(ull v) {
    float2 r;
    asm("mov.b64 {%0, %1}, %2;" : "=f"(r.x), "=f"(r.y) : "l"(v));
    return r;
}

// ---------------- scratch (device globals; no allocs allowed) ----------------
__device__ float g_sent[T_LEN * BB * SENT_D];
__device__ float g_preF[(size_t)T_LEN * BB * G4];
__device__ float g_preB[(size_t)T_LEN * BB * G4];
__device__ float g_in2[(size_t)T_LEN * BB * 1024];
__device__ float g_fwd2[(size_t)T_LEN * BB * UU];
__device__ float g_back2[(size_t)T_LEN * BB * UU];

__device__ float g_Wx1f[SENT_D * G4], g_Wx1b[SENT_D * G4];
__device__ float g_Wh1f[UU * G4],     g_Wh1b[UU * G4];   // k-paired [256][4096]
__device__ float g_Wx2f[1024 * G4],   g_Wx2b[1024 * G4];
__device__ float g_Wh2f[UU * G4],     g_Wh2b[UU * G4];   // k-paired
__device__ float g_bv1f[G4], g_bv1b[G4], g_bv2f[G4], g_bv2b[G4];

__device__ float g_hFa[BB * UU], g_hFb[BB * UU];
__device__ float g_hBa[BB * UU], g_hBb[BB * UU];
__device__ float g_cF[BB * UU],  g_cB[BB * UU];

__device__ float g_hi_s[BB * 8192];
__device__ float g_hi_l[BB * 6144];
__device__ float g_part_s[16 * BB * HD];
__device__ float g_part_l[12 * BB * HD];
__device__ float g_hs[BB * HD], g_hl[BB * HD];

// ---------------- weight packing ----------------------------------------------
// Wx: column n = u*4 + k (gate-interleaved).
// Wh: additionally k-pair-interleaved: Wh[(kd>>1)*4096 + n*2 + (kd&1)]
__global__ void pack_lstm(const float* __restrict__ W, const float* __restrict__ b,
                          float* __restrict__ Wx, float* __restrict__ Wh,
                          float* __restrict__ bv, int din) {
    int total = 4 * (din + UU) * UU;
    int stride = gridDim.x * blockDim.x;
    for (int idx = blockIdx.x * blockDim.x + threadIdx.x; idx < total; idx += stride) {
        int k = idx / ((din + UU) * UU);
        int rem = idx - k * ((din + UU) * UU);
        int d = rem / UU;
        int u = rem - d * UU;
        float v = W[idx];
        int n = u * 4 + k;
        if (d < din) {
            Wx[(size_t)d * G4 + n] = v;
        } else {
            int kd = d - din;
            Wh[(size_t)(kd >> 1) * 4096 + n * 2 + (kd & 1)] = v;
        }
    }
    for (int i = blockIdx.x * blockDim.x + threadIdx.x; i < G4; i += stride) {
        int k = i & 3, u = i >> 2;
        bv[i] = b[k * UU + u];
    }
}

// ---------------- embedding gather + concat ----------------------------------
__global__ void embed_kernel(const float* __restrict__ we, const float* __restrict__ te,
                             const int* __restrict__ wi, const int* __restrict__ ti) {
    int idx = blockIdx.x * blockDim.x + threadIdx.x;
    int tb = idx / SENT_D;
    int j = idx - tb * SENT_D;
    float v;
    if (j < 256) v = we[(size_t)wi[tb] * 256 + j];
    else         v = te[(size_t)ti[tb] * 64 + (j - 256)];
    g_sent[idx] = v;
}

// ---------------- LSTM state init --------------------------------------------
__global__ void init_states(const float* __restrict__ c0f, const float* __restrict__ c0b) {
    int idx = blockIdx.x * blockDim.x + threadIdx.x;   // B*U = 32768
    int u = idx & (UU - 1);
    float cf = c0f[u], cb = c0b[u];
    g_cF[idx] = cf;  g_hFa[idx] = tanhf(cf);
    g_cB[idx] = cb;  g_hBa[idx] = tanhf(cb);
}

// ---------------- big SGEMM: C = A@B, 128x128 tiles, FFMA2 (R4 proven) -------
__global__ void __launch_bounds__(256) sgemm_128x128(
    const float* __restrict__ A, const float* __restrict__ B, float* __restrict__ C,
    int K, int lda, int ldb, int ldc) {
    __shared__ float As[16][132];   // As[kk][m]
    __shared__ float Bs[16][132];   // Bs[kk][n]
    int m0 = blockIdx.y * 128, n0 = blockIdx.x * 128;
    int tid = threadIdx.x;
    int tx = tid & 15, ty = tid >> 4;
    ull acc[4][8];
#pragma unroll
    for (int p = 0; p < 4; p++)
#pragma unroll
        for (int j = 0; j < 8; j++) acc[p][j] = 0ULL;

    int ar = tid >> 2, ac = (tid & 3) * 4;
    int bk = tid >> 5, bn = (tid & 31) * 4;

    for (int k0 = 0; k0 < K; k0 += 16) {
        float4 a0 = *(const float4*)(A + (size_t)(m0 + ar) * lda + k0 + ac);
        float4 a1 = *(const float4*)(A + (size_t)(m0 + ar + 64) * lda + k0 + ac);
        float4 b0 = *(const float4*)(B + (size_t)(k0 + bk) * ldb + n0 + bn);
        float4 b1 = *(const float4*)(B + (size_t)(k0 + bk + 8) * ldb + n0 + bn);
        __syncthreads();
        As[ac + 0][ar] = a0.x; As[ac + 1][ar] = a0.y; As[ac + 2][ar] = a0.z; As[ac + 3][ar] = a0.w;
        As[ac + 0][ar + 64] = a1.x; As[ac + 1][ar + 64] = a1.y; As[ac + 2][ar + 64] = a1.z; As[ac + 3][ar + 64] = a1.w;
        *(float4*)&Bs[bk][bn] = b0;
        *(float4*)&Bs[bk + 8][bn] = b1;
        __syncthreads();
#pragma unroll
        for (int kk = 0; kk < 16; kk++) {
            ull ap[4];
#pragma unroll
            for (int p = 0; p < 4; p++)
                ap[p] = *(const ull*)&As[kk][ty * 8 + 2 * p];
            float4 bv0 = *(float4*)&Bs[kk][tx * 8];
            float4 bv1 = *(float4*)&Bs[kk][tx * 8 + 4];
            ull bd[8] = {dup2(bv0.x), dup2(bv0.y), dup2(bv0.z), dup2(bv0.w),
                         dup2(bv1.x), dup2(bv1.y), dup2(bv1.z), dup2(bv1.w)};
#pragma unroll
            for (int p = 0; p < 4; p++)
#pragma unroll
                for (int j = 0; j < 8; j++) fma2(acc[p][j], ap[p], bd[j]);
        }
    }
#pragma unroll
    for (int p = 0; p < 4; p++) {
        float v0[8], v1[8];
#pragma unroll
        for (int j = 0; j < 8; j++) {
            float2 t = unpack2(acc[p][j]);
            v0[j] = t.x; v1[j] = t.y;
        }
        float* c0 = C + (size_t)(m0 + ty * 8 + 2 * p) * ldc + n0 + tx * 8;
        float* c1 = c0 + ldc;
        *(float4*)c0 = make_float4(v0[0], v0[1], v0[2], v0[3]);
        *(float4*)(c0 + 4) = make_float4(v0[4], v0[5], v0[6], v0[7]);
        *(float4*)c1 = make_float4(v1[0], v1[1], v1[2], v1[3]);
        *(float4*)(c1 + 4) = make_float4(v1[4], v1[5], v1[6], v1[7]);
    }
}

// ---------------- one recurrent step, both dirs, 256 threads -----------------
// grid = 128 CTAs: blk>>6 = dir, blk&63 = 32-wide gate tile (8 units).
// Thread tile: 2 batch rows x 4 gates (1 unit); FFMA2 packs k-pairs.
// Double-buffered 32-k staging blocks, 1 barrier per block, reg prefetch.
#define ASTR44 44
__global__ void __launch_bounds__(256) lstm_step(
    const float* __restrict__ preF, const float* __restrict__ preB,
    const float* __restrict__ WpF,  const float* __restrict__ WpB,
    const float* __restrict__ bvF,  const float* __restrict__ bvB,
    const float* __restrict__ hinF, float* __restrict__ houtF,
    const float* __restrict__ hinB, float* __restrict__ houtB,
    float* __restrict__ outF, float* __restrict__ outB,
    int ostride, int tF, int tB) {
    __shared__ __align__(16) float As[2][64 * ASTR44];  // [buf][b*44 + k(0..31)]
    __shared__ __align__(16) float Bs[2][16 * 64];      // [buf][kk2*64 + c]

    int blk = blockIdx.x;
    int dir = blk >> 6;
    int nb  = blk & 63;
    int n0  = nb * 32;

    const float* pre = dir ? preB : preF;
    const float* Wp  = dir ? WpB : WpF;
    const float* bv  = dir ? bvB : bvF;
    const float* hin = dir ? hinB : hinF;
    float* hout = dir ? houtB : houtF;
    float* cst  = dir ? g_cB : g_cF;
    float* outp = dir ? outB : outF;
    int t = dir ? tB : tF;

    int tid = threadIdx.x;
    int tx = tid & 7, ty = tid >> 3;          // tx: unit, ty: b-pair (0..31)
    int b0 = ty * 2, b1 = b0 + 1;
    int u = nb * 8 + tx;

    // early independent loads (latency hides under the k-loop)
    float4 pv0 = *(const float4*)(pre + ((size_t)t * BB + b0) * G4 + n0 + tx * 4);
    float4 pv1 = *(const float4*)(pre + ((size_t)t * BB + b1) * G4 + n0 + tx * 4);
    float4 bb4 = *(const float4*)(bv + n0 + tx * 4);
    float cv0 = cst[b0 * UU + u];
    float cv1 = cst[b1 * UU + u];

    // staging assignments
    int sb = tid >> 2, sseg = (tid & 3) * 4;  // A: row sb, 8 floats (2 float4)
    int wr = tid >> 4, wc = (tid & 15) * 4;   // W: 16 kpair-rows x 64

    // prologue: stage block k0=0
    {
        float4 a40 = *(const float4*)(hin + sb * UU + sseg);
        float4 a41 = *(const float4*)(hin + sb * UU + sseg + 16);
        float4 w4  = *(const float4*)(Wp + (size_t)wr * 4096 + n0 * 2 + wc);
        *(float4*)&As[0][sb * ASTR44 + sseg]      = a40;
        *(float4*)&As[0][sb * ASTR44 + sseg + 16] = a41;
        *(float4*)&Bs[0][wr * 64 + wc] = w4;
    }
    __syncthreads();

    ull acc[2][4];
#pragma unroll
    for (int i = 0; i < 2; i++)
#pragma unroll
        for (int j = 0; j < 4; j++) acc[i][j] = 0ULL;

    int p = 0;
    for (int k0 = 0; k0 < UU; k0 += 32, p ^= 1) {
        int kn = k0 + 32;
        float4 na0, na1, nw;
        bool more = (kn < UU);
        if (more) {
            na0 = *(const float4*)(hin + sb * UU + kn + sseg);
            na1 = *(const float4*)(hin + sb * UU + kn + sseg + 16);
            nw  = *(const float4*)(Wp + (size_t)((kn >> 1) + wr) * 4096 + n0 * 2 + wc);
        }
        const float* Ap = As[p];
        const float* Bp = Bs[p];
#pragma unroll
        for (int kk2 = 0; kk2 < 16; kk2++) {
            ull a0 = *(const ull*)(Ap + b0 * ASTR44 + kk2 * 2);
            ull a1 = *(const ull*)(Ap + b1 * ASTR44 + kk2 * 2);
            ulonglong2 wA = *(const ulonglong2*)(Bp + kk2 * 64 + tx * 8);
            ulonglong2 wB = *(const ulonglong2*)(Bp + kk2 * 64 + tx * 8 + 4);
            fma2(acc[0][0], a0, wA.x); fma2(acc[0][1], a0, wA.y);
            fma2(acc[0][2], a0, wB.x); fma2(acc[0][3], a0, wB.y);
            fma2(acc[1][0], a1, wA.x); fma2(acc[1][1], a1, wA.y);
            fma2(acc[1][2], a1, wB.x); fma2(acc[1][3], a1, wB.y);
        }
        if (more) {
            *(float4*)&As[p ^ 1][sb * ASTR44 + sseg]      = na0;
            *(float4*)&As[p ^ 1][sb * ASTR44 + sseg + 16] = na1;
            *(float4*)&Bs[p ^ 1][wr * 64 + wc] = nw;
        }
        __syncthreads();
    }

    // epilogue: fold k-even/odd partials, gates, state update
#pragma unroll
    for (int i = 0; i < 2; i++) {
        int b = (i == 0) ? b0 : b1;
        float4 pv = (i == 0) ? pv0 : pv1;
        float cv  = (i == 0) ? cv0 : cv1;
        float2 e0 = unpack2(acc[i][0]);
        float2 e1 = unpack2(acc[i][1]);
        float2 e2 = unpack2(acc[i][2]);
        float2 e3 = unpack2(acc[i][3]);
        float gi = e0.x + e0.y + pv.x + bb4.x;
        float gf = e1.x + e1.y + pv.y + bb4.y;
        float go = e2.x + e2.y + pv.z + bb4.z;
        float gg = e3.x + e3.y + pv.w + bb4.w;
        float ig = 1.f / (1.f + expf(-gi));
        float fg = 1.f / (1.f + expf(-gf));
        float og = 1.f / (1.f + expf(-go));
        float gt = tanhf(gg);
        float c = fg * cv + ig * gt;
        float h = og * tanhf(c);
        cst[b * UU + u] = c;
        hout[b * UU + u] = h;
        outp[((size_t)t * BB + b) * ostride + u] = h;
    }
}

// ---------------- span feature gather ----------------------------------------
__global__ void build_hi(const int* __restrict__ sl, const int* __restrict__ sr,
                         const int* __restrict__ ll, const int* __restrict__ lr) {
    int idx = blockIdx.x * blockDim.x + threadIdx.x;
    const int NS = BB * 4 * 2048;
    int b, s, c, le, ri;
    float* dst;
    if (idx < NS) {
        b = idx / (4 * 2048); int r = idx - b * (4 * 2048);
        s = r / 2048; c = r - s * 2048;
        le = sl[b * 4 + s]; ri = sr[b * 4 + s];
        dst = g_hi_s + (size_t)b * 8192 + s * 2048 + c;
    } else {
        int j = idx - NS;
        b = j / (3 * 2048); int r = j - b * (3 * 2048);
        s = r / 2048; c = r - s * 2048;
        le = ll[b * 3 + s]; ri = lr[b * 3 + s];
        dst = g_hi_l + (size_t)b * 6144 + s * 2048 + c;
    }
    float v;
    if (c < 512) {
        v = g_in2[((size_t)ri * BB + b) * 1024 + c] - g_in2[((size_t)(le - 1) * BB + b) * 1024 + c];
    } else if (c < 1024) {
        int u = c - 512;
        v = g_fwd2[((size_t)ri * BB + b) * UU + u] - g_fwd2[((size_t)(le - 1) * BB + b) * UU + u];
    } else if (c < 1536) {
        int u = c - 1024;
        v = g_in2[((size_t)le * BB + b) * 1024 + 512 + u] - g_in2[((size_t)(ri + 1) * BB + b) * 1024 + 512 + u];
    } else {
        int u = c - 1536;
        v = g_back2[((size_t)le * BB + b) * UU + u] - g_back2[((size_t)(ri + 1) * BB + b) * UU + u];
    }
    *dst = v;
}

// ---------------- span hidden GEMM: M=64, split-K into partial planes --------
__global__ void __launch_bounds__(256) span_gemm(
    const float* __restrict__ A, int lda, const float* __restrict__ B,
    float* __restrict__ Cpart) {
    __shared__ float AsT[16][68];
    __shared__ float Bs[16][68];
    int n0 = blockIdx.x * 64;
    int kbase = blockIdx.y * 512;
    int tid = threadIdx.x;
    int tx = tid & 15, ty = tid >> 4;
    float acc[4][4] = {{0}};
    int ab = tid >> 2, aseg = (tid & 3) * 4;
    int bkk = tid >> 4, bnn = (tid & 15) * 4;
    for (int k0 = kbase; k0 < kbase + 512; k0 += 16) {
        float4 av = *(const float4*)(A + (size_t)ab * lda + k0 + aseg);
        float4 wv = *(const float4*)(B + (size_t)(k0 + bkk) * HD + n0 + bnn);
        __syncthreads();
        AsT[aseg + 0][ab] = av.x; AsT[aseg + 1][ab] = av.y;
        AsT[aseg + 2][ab] = av.z; AsT[aseg + 3][ab] = av.w;
        *(float4*)&Bs[bkk][bnn] = wv;
        __syncthreads();
#pragma unroll
        for (int kk = 0; kk < 16; kk++) {
            float4 a = *(float4*)&AsT[kk][ty * 4];
            float4 w = *(float4*)&Bs[kk][tx * 4];
            float aa[4] = {a.x, a.y, a.z, a.w};
            float ww[4] = {w.x, w.y, w.z, w.w};
#pragma unroll
            for (int i = 0; i < 4; i++)
#pragma unroll
                for (int j = 0; j < 4; j++) acc[i][j] += aa[i] * ww[j];
        }
    }
#pragma unroll
    for (int i = 0; i < 4; i++) {
        int b = ty * 4 + i;
        float4 v = {acc[i][0], acc[i][1], acc[i][2], acc[i][3]};
        *(float4*)(Cpart + ((size_t)blockIdx.y * BB + b) * HD + n0 + tx * 4) = v;
    }
}

__global__ void reduce_relu(const float* __restrict__ part, int nch,
                            const float* __restrict__ bias, float* __restrict__ outh) {
    int idx = blockIdx.x * blockDim.x + threadIdx.x;
    int n = idx & (HD - 1);
    float s = bias[n];
    for (int ch = 0; ch < nch; ch++) s += part[(size_t)ch * BB * HD + idx];
    outh[idx] = fmaxf(s, 0.f);
}

// ---------------- output heads ------------------------------------------------
__global__ void out_heads(const float* __restrict__ soW, const float* __restrict__ sob,
                          const float* __restrict__ loW, const float* __restrict__ lob,
                          float* __restrict__ out) {
    __shared__ float s1[HD], s2[HD];
    int b = blockIdx.x, tid = threadIdx.x;
    for (int i = tid; i < HD; i += blockDim.x) {
        s1[i] = g_hs[b * HD + i];
        s2[i] = g_hl[b * HD + i];
    }
    __syncthreads();
    if (tid < 2) {
        float s = sob[tid];
        for (int k = 0; k < HD; k++) s += s1[k] * soW[k * 2 + tid];
        out[b * 2 + tid] = s;
    } else if (tid < 34) {
        int j = tid - 2;
        float s = lob[j];
        for (int k = 0; k < HD; k++) s += s2[k] * loW[k * 32 + j];
        out[128 + b * 32 + j] = s;
    }
}

// ---------------- host driver --------------------------------------------------
static float* sym(const void* symbol) {
    void* p = nullptr;
    cudaGetSymbolAddress(&p, symbol);
    return (float*)p;
}

extern "C" void kernel_launch(void* const* d_in, const int* in_sizes, int n_in,
                              void* d_out, int out_size) {
    const float* word_emb = (const float*)d_in[0];
    const float* tag_emb  = (const float*)d_in[1];
    const float* l1f_W = (const float*)d_in[2];
    const float* l1f_b = (const float*)d_in[3];
    const float* l1f_c0 = (const float*)d_in[4];
    const float* l1b_W = (const float*)d_in[5];
    const float* l1b_b = (const float*)d_in[6];
    const float* l1b_c0 = (const float*)d_in[7];
    const float* l2f_W = (const float*)d_in[8];
    const float* l2f_b = (const float*)d_in[9];
    const float* l2f_c0 = (const float*)d_in[10];
    const float* l2b_W = (const float*)d_in[11];
    const float* l2b_b = (const float*)d_in[12];
    const float* l2b_c0 = (const float*)d_in[13];
    const float* sh_W = (const float*)d_in[14];
    const float* sh_b = (const float*)d_in[15];
    const float* so_W = (const float*)d_in[16];
    const float* so_b = (const float*)d_in[17];
    const float* lh_W = (const float*)d_in[18];
    const float* lh_b = (const float*)d_in[19];
    const float* lo_W = (const float*)d_in[20];
    const float* lo_b = (const float*)d_in[21];
    const int* word_inds = (const int*)d_in[22];
    const int* tag_inds  = (const int*)d_in[23];
    const int* s_lefts  = (const int*)d_in[24];
    const int* s_rights = (const int*)d_in[25];
    const int* l_lefts  = (const int*)d_in[26];
    const int* l_rights = (const int*)d_in[27];
    float* out = (float*)d_out;

    float* p_sent  = sym(g_sent);
    float* p_preF  = sym(g_preF);
    float* p_preB  = sym(g_preB);
    float* p_in2   = sym(g_in2);
    float* p_fwd2  = sym(g_fwd2);
    float* p_back2 = sym(g_back2);
    float* p_Wx1f = sym(g_Wx1f); float* p_Wx1b = sym(g_Wx1b);
    float* p_Wh1f = sym(g_Wh1f); float* p_Wh1b = sym(g_Wh1b);
    float* p_Wx2f = sym(g_Wx2f); float* p_Wx2b = sym(g_Wx2b);
    float* p_Wh2f = sym(g_Wh2f); float* p_Wh2b = sym(g_Wh2b);
    float* p_bv1f = sym(g_bv1f); float* p_bv1b = sym(g_bv1b);
    float* p_bv2f = sym(g_bv2f); float* p_bv2b = sym(g_bv2b);
    float* p_hFa = sym(g_hFa); float* p_hFb = sym(g_hFb);
    float* p_hBa = sym(g_hBa); float* p_hBb = sym(g_hBb);
    float* p_hi_s = sym(g_hi_s); float* p_hi_l = sym(g_hi_l);
    float* p_part_s = sym(g_part_s); float* p_part_l = sym(g_part_l);
    float* p_hs = sym(g_hs); float* p_hl = sym(g_hl);

    // 1) pack weights
    pack_lstm<<<2048, 256>>>(l1f_W, l1f_b, p_Wx1f, p_Wh1f, p_bv1f, SENT_D);
    pack_lstm<<<2048, 256>>>(l1b_W, l1b_b, p_Wx1b, p_Wh1b, p_bv1b, SENT_D);
    pack_lstm<<<4096, 256>>>(l2f_W, l2f_b, p_Wx2f, p_Wh2f, p_bv2f, 1024);
    pack_lstm<<<4096, 256>>>(l2b_W, l2b_b, p_Wx2b, p_Wh2b, p_bv2b, 1024);

    // 2) embeddings
    embed_kernel<<<(T_LEN * BB * SENT_D) / 256, 256>>>(word_emb, tag_emb, word_inds, tag_inds);

    // 3) layer-1 input projections (16384 x 320 x 2048)
    dim3 gpre(G4 / 128, (T_LEN * BB) / 128);
    sgemm_128x128<<<gpre, 256>>>(p_sent, p_Wx1f, p_preF, SENT_D, SENT_D, G4, G4);
    sgemm_128x128<<<gpre, 256>>>(p_sent, p_Wx1b, p_preB, SENT_D, SENT_D, G4, G4);

    // 4) layer-1 recurrence
    init_states<<<(BB * UU) / 256, 256>>>(l1f_c0, l1b_c0);
    for (int s = 0; s < T_LEN; s++) {
        const float* hinF = (s & 1) ? p_hFb : p_hFa;
        float* houtF      = (s & 1) ? p_hFa : p_hFb;
        const float* hinB = (s & 1) ? p_hBb : p_hBa;
        float* houtB      = (s & 1) ? p_hBa : p_hBb;
        lstm_step<<<128, 256>>>(p_preF, p_preB, p_Wh1f, p_Wh1b, p_bv1f, p_bv1b,
                                hinF, houtF, hinB, houtB,
                                p_in2, p_in2 + 512, 1024, s, T_LEN - 1 - s);
    }

    // 5) layer-2 input projections (16384 x 1024 x 2048)
    sgemm_128x128<<<gpre, 256>>>(p_in2, p_Wx2f, p_preF, 1024, 1024, G4, G4);
    sgemm_128x128<<<gpre, 256>>>(p_in2, p_Wx2b, p_preB, 1024, 1024, G4, G4);

    // 6) layer-2 recurrence
    init_states<<<(BB * UU) / 256, 256>>>(l2f_c0, l2b_c0);
    for (int s = 0; s < T_LEN; s++) {
        const float* hinF = (s & 1) ? p_hFb : p_hFa;
        float* houtF      = (s & 1) ? p_hFa : p_hFb;
        const float* hinB = (s & 1) ? p_hBb : p_hBa;
        float* houtB      = (s & 1) ? p_hBa : p_hBb;
        lstm_step<<<128, 256>>>(p_preF, p_preB, p_Wh2f, p_Wh2b, p_bv2f, p_bv2b,
                                hinF, houtF, hinB, houtB,
                                p_fwd2, p_back2, UU, s, T_LEN - 1 - s);
    }

    // 7) span features
    build_hi<<<(BB * 7 * 2048) / 256, 256>>>(s_lefts, s_rights, l_lefts, l_rights);

    // 8) span hidden layers
    span_gemm<<<dim3(HD / 64, 16), 256>>>(p_hi_s, 8192, sh_W, p_part_s);
    span_gemm<<<dim3(HD / 64, 12), 256>>>(p_hi_l, 6144, lh_W, p_part_l);
    reduce_relu<<<(BB * HD) / 256, 256>>>(p_part_s, 16, sh_b, p_hs);
    reduce_relu<<<(BB * HD) / 256, 256>>>(p_part_l, 12, lh_b, p_hl);

    // 9) output heads
    out_heads<<<BB, 128>>>(so_W, so_b, lo_W, lo_b, out);
}

// round 8
// speedup vs baseline: 1.1456x; 1.0659x over previous
#include <cuda_runtime.h>
#include <math.h>
#include <stdint.h>

#define T_LEN 256
#define BB 64
#define SENT_D 320
#define UU 512
#define G4 2048
#define HD 1024
#define MTOT (T_LEN * BB)          // 16384

typedef unsigned long long ull;

// ---------------- packed f32x2 + cp.async helpers ----------------------------
__device__ __forceinline__ void fma2(ull& d, ull a, ull b) {
    asm("fma.rn.f32x2 %0, %1, %2, %0;" : "+l"(d) : "l"(a), "l"(b));
}
__device__ __forceinline__ ull dup2(float x) {
    ull r;
    asm("mov.b64 %0, {%1, %1};" : "=l"(r) : "f"(x));
    return r;
}
__device__ __forceinline__ float2 unpack2(ull v) {
    float2 r;
    asm("mov.b64 {%0, %1}, %2;" : "=f"(r.x), "=f"(r.y) : "l"(v));
    return r;
}
__device__ __forceinline__ void cp_async16(uint32_t saddr, const void* gptr) {
    asm volatile("cp.async.cg.shared.global [%0], [%1], 16;" :: "r"(saddr), "l"(gptr));
}
__device__ __forceinline__ void cp_commit() {
    asm volatile("cp.async.commit_group;" ::: "memory");
}
template<int N> __device__ __forceinline__ void cp_wait() {
    asm volatile("cp.async.wait_group %0;" :: "n"(N) : "memory");
}

// ---------------- scratch (device globals; no allocs allowed) ----------------
__device__ float g_sent[MTOT * SENT_D];
__device__ float g_sentT[SENT_D * MTOT];                 // [320][16384]
__device__ float g_preF[(size_t)MTOT * G4];
__device__ float g_preB[(size_t)MTOT * G4];
__device__ float g_in2[(size_t)MTOT * 1024];             // [t][b][c]
__device__ float g_in2T[(size_t)1024 * MTOT];            // [c][t*64+b]
__device__ float g_fwd2[(size_t)MTOT * UU];
__device__ float g_back2[(size_t)MTOT * UU];

__device__ float g_Wx1f[SENT_D * G4], g_Wx1b[SENT_D * G4];
__device__ float g_Wh1f[UU * G4],     g_Wh1b[UU * G4];   // k-paired [256][4096]
__device__ float g_Wx2f[1024 * G4],   g_Wx2b[1024 * G4];
__device__ float g_Wh2f[UU * G4],     g_Wh2b[UU * G4];   // k-paired
__device__ float g_bv1f[G4], g_bv1b[G4], g_bv2f[G4], g_bv2b[G4];

__device__ float g_hFa[BB * UU], g_hFb[BB * UU];
__device__ float g_hBa[BB * UU], g_hBb[BB * UU];
__device__ float g_cF[BB * UU],  g_cB[BB * UU];

__device__ float g_hi_s[BB * 8192];
__device__ float g_hi_l[BB * 6144];
__device__ float g_part_s[16 * BB * HD];
__device__ float g_part_l[12 * BB * HD];
__device__ float g_hs[BB * HD], g_hl[BB * HD];

// ---------------- weight packing ----------------------------------------------
__global__ void pack_lstm(const float* __restrict__ W, const float* __restrict__ b,
                          float* __restrict__ Wx, float* __restrict__ Wh,
                          float* __restrict__ bv, int din) {
    int total = 4 * (din + UU) * UU;
    int stride = gridDim.x * blockDim.x;
    for (int idx = blockIdx.x * blockDim.x + threadIdx.x; idx < total; idx += stride) {
        int k = idx / ((din + UU) * UU);
        int rem = idx - k * ((din + UU) * UU);
        int d = rem / UU;
        int u = rem - d * UU;
        float v = W[idx];
        int n = u * 4 + k;
        if (d < din) {
            Wx[(size_t)d * G4 + n] = v;
        } else {
            int kd = d - din;
            Wh[(size_t)(kd >> 1) * 4096 + n * 2 + (kd & 1)] = v;
        }
    }
    for (int i = blockIdx.x * blockDim.x + threadIdx.x; i < G4; i += stride) {
        int k = i & 3, u = i >> 2;
        bv[i] = b[k * UU + u];
    }
}

// ---------------- embedding gather + concat ----------------------------------
__global__ void embed_kernel(const float* __restrict__ we, const float* __restrict__ te,
                             const int* __restrict__ wi, const int* __restrict__ ti) {
    int idx = blockIdx.x * blockDim.x + threadIdx.x;
    int tb = idx / SENT_D;
    int j = idx - tb * SENT_D;
    float v;
    if (j < 256) v = we[(size_t)wi[tb] * 256 + j];
    else         v = te[(size_t)ti[tb] * 64 + (j - 256)];
    g_sent[idx] = v;
}

// ---------------- tiled transpose: dst[c][r] = src[r][c] ----------------------
__global__ void transpose32(const float* __restrict__ src, float* __restrict__ dst,
                            int R, int Cc) {
    __shared__ float tl[32][33];
    int c0 = blockIdx.x * 32, r0 = blockIdx.y * 32;
    int tx = threadIdx.x, ty = threadIdx.y;   // 32 x 8
#pragma unroll
    for (int i = 0; i < 32; i += 8)
        tl[ty + i][tx] = src[(size_t)(r0 + ty + i) * Cc + c0 + tx];
    __syncthreads();
#pragma unroll
    for (int i = 0; i < 32; i += 8)
        dst[(size_t)(c0 + ty + i) * R + r0 + tx] = tl[tx][ty + i];
}

// ---------------- LSTM state init --------------------------------------------
__global__ void init_states(const float* __restrict__ c0f, const float* __restrict__ c0b) {
    int idx = blockIdx.x * blockDim.x + threadIdx.x;   // B*U = 32768
    int u = idx & (UU - 1);
    float cf = c0f[u], cb = c0b[u];
    g_cF[idx] = cf;  g_hFa[idx] = tanhf(cf);
    g_cB[idx] = cb;  g_hBa[idx] = tanhf(cb);
}

// ---------------- big GEMM: C = AT^T @ B, cp.async double-buffered ------------
// AT: [K][ldat] (pre-transposed A), B: [K][ldb], C: [M][ldc]
__global__ void __launch_bounds__(256) sgemm_nt(
    const float* __restrict__ AT, const float* __restrict__ B, float* __restrict__ C,
    int K, int ldat, int ldb, int ldc) {
    __shared__ float As[2][16 * 132];
    __shared__ float Bs[2][16 * 132];
    int m0 = blockIdx.y * 128, n0 = blockIdx.x * 128;
    int tid = threadIdx.x;
    int tx = tid & 15, ty = tid >> 4;
    uint32_t as0 = (uint32_t)__cvta_generic_to_shared(&As[0][0]);
    uint32_t bs0 = (uint32_t)__cvta_generic_to_shared(&Bs[0][0]);
    int akk = tid >> 5, aoff = (tid & 31) * 4;

    ull acc[4][8];
#pragma unroll
    for (int p = 0; p < 4; p++)
#pragma unroll
        for (int j = 0; j < 8; j++) acc[p][j] = 0ULL;

#define SG_STAGE(pp, kk0) do { \
        cp_async16(as0 + (uint32_t)(((pp) * 2112 + akk * 132 + aoff) * 4), \
                   AT + (size_t)((kk0) + akk) * ldat + m0 + aoff); \
        cp_async16(as0 + (uint32_t)(((pp) * 2112 + (akk + 8) * 132 + aoff) * 4), \
                   AT + (size_t)((kk0) + akk + 8) * ldat + m0 + aoff); \
        cp_async16(bs0 + (uint32_t)(((pp) * 2112 + akk * 132 + aoff) * 4), \
                   B + (size_t)((kk0) + akk) * ldb + n0 + aoff); \
        cp_async16(bs0 + (uint32_t)(((pp) * 2112 + (akk + 8) * 132 + aoff) * 4), \
                   B + (size_t)((kk0) + akk + 8) * ldb + n0 + aoff); \
    } while (0)

    SG_STAGE(0, 0);
    cp_commit();

    int p = 0;
    for (int k0 = 0; k0 < K; k0 += 16, p ^= 1) {
        if (k0 + 16 < K) {
            SG_STAGE(p ^ 1, k0 + 16);
            cp_commit();
            cp_wait<1>();
        } else {
            cp_wait<0>();
        }
        __syncthreads();
        const float* Ap = &As[p][0];
        const float* Bp = &Bs[p][0];
#pragma unroll
        for (int kk = 0; kk < 16; kk++) {
            ull ap[4];
#pragma unroll
            for (int q = 0; q < 4; q++)
                ap[q] = *(const ull*)(Ap + kk * 132 + ty * 8 + 2 * q);
            float4 bv0 = *(const float4*)(Bp + kk * 132 + tx * 8);
            float4 bv1 = *(const float4*)(Bp + kk * 132 + tx * 8 + 4);
            ull bd[8] = {dup2(bv0.x), dup2(bv0.y), dup2(bv0.z), dup2(bv0.w),
                         dup2(bv1.x), dup2(bv1.y), dup2(bv1.z), dup2(bv1.w)};
#pragma unroll
            for (int q = 0; q < 4; q++)
#pragma unroll
                for (int j = 0; j < 8; j++) fma2(acc[q][j], ap[q], bd[j]);
        }
        __syncthreads();
    }
#undef SG_STAGE

#pragma unroll
    for (int q = 0; q < 4; q++) {
        float v0[8], v1[8];
#pragma unroll
        for (int j = 0; j < 8; j++) {
            float2 t = unpack2(acc[q][j]);
            v0[j] = t.x; v1[j] = t.y;
        }
        float* c0 = C + (size_t)(m0 + ty * 8 + 2 * q) * ldc + n0 + tx * 8;
        float* c1 = c0 + ldc;
        *(float4*)c0 = make_float4(v0[0], v0[1], v0[2], v0[3]);
        *(float4*)(c0 + 4) = make_float4(v0[4], v0[5], v0[6], v0[7]);
        *(float4*)c1 = make_float4(v1[0], v1[1], v1[2], v1[3]);
        *(float4*)(c1 + 4) = make_float4(v1[4], v1[5], v1[6], v1[7]);
    }
}

// ---------------- one recurrent step: 128 CTAs x 256 thr, cp.async 4-stage ----
// blk>>6 = dir, blk&63 = 32-wide gate tile (8 units). Thread: 2b x 4g, FFMA2.
// smem: As[4][64*36] (h block, 32 k per stage), Bs[4][16*64] (k-paired W block)
__global__ void __launch_bounds__(256) lstm_step(
    const float* __restrict__ preF, const float* __restrict__ preB,
    const float* __restrict__ WpF,  const float* __restrict__ WpB,
    const float* __restrict__ bvF,  const float* __restrict__ bvB,
    const float* __restrict__ hinF, float* __restrict__ houtF,
    const float* __restrict__ hinB, float* __restrict__ houtB,
    float* __restrict__ outF, float* __restrict__ outB,
    float* __restrict__ outTF, float* __restrict__ outTB,
    int ostride, int tF, int tB) {
    extern __shared__ float sm[];
    float* Asm = sm;                    // 4 * 2304 floats
    float* Bsm = sm + 4 * 2304;         // 4 * 1024 floats

    int blk = blockIdx.x;
    int dir = blk >> 6;
    int nb  = blk & 63;
    int n0  = nb * 32;

    const float* pre = dir ? preB : preF;
    const float* Wp  = dir ? WpB : WpF;
    const float* bv  = dir ? bvB : bvF;
    const float* hin = dir ? hinB : hinF;
    float* hout = dir ? houtB : houtF;
    float* cst  = dir ? g_cB : g_cF;
    float* outp = dir ? outB : outF;
    float* outT = dir ? outTB : outTF;
    int t = dir ? tB : tF;

    int tid = threadIdx.x;
    int tx = tid & 7, ty = tid >> 3;          // tx: unit, ty: b-pair (0..31)
    int b0 = ty * 2, b1 = b0 + 1;
    int u = nb * 8 + tx;

    uint32_t asb = (uint32_t)__cvta_generic_to_shared(Asm);
    uint32_t bsb = (uint32_t)__cvta_generic_to_shared(Bsm);

    // early independent loads (latency hides under the k-loop)
    float4 pv0 = *(const float4*)(pre + ((size_t)t * BB + b0) * G4 + n0 + tx * 4);
    float4 pv1 = *(const float4*)(pre + ((size_t)t * BB + b1) * G4 + n0 + tx * 4);
    float4 bb4 = *(const float4*)(bv + n0 + tx * 4);
    float cv0 = cst[b0 * UU + u];
    float cv1 = cst[b1 * UU + u];

    // staging chunk assignments
    int ar0 = tid >> 3,        ao0 = (tid & 7) * 4;          // A chunk 1
    int ar1 = (tid + 256) >> 3, ao1 = (tid & 7) * 4;         // A chunk 2 (rows 32..63)
    int br  = tid >> 4,        bo  = (tid & 15) * 4;         // B chunk

#define LS_STAGE(st, kk0) do { \
        cp_async16(asb + (uint32_t)((((st) * 2304) + ar0 * 36 + ao0) * 4), \
                   hin + ar0 * UU + (kk0) + ao0); \
        cp_async16(asb + (uint32_t)((((st) * 2304) + ar1 * 36 + ao1) * 4), \
                   hin + ar1 * UU + (kk0) + ao1); \
        cp_async16(bsb + (uint32_t)((((st) * 1024) + br * 64 + bo) * 4), \
                   Wp + (size_t)(((kk0) >> 1) + br) * 4096 + n0 * 2 + bo); \
    } while (0)

    LS_STAGE(0, 0);  cp_commit();
    LS_STAGE(1, 32); cp_commit();
    LS_STAGE(2, 64); cp_commit();

    ull acc[2][4];
#pragma unroll
    for (int i = 0; i < 2; i++)
#pragma unroll
        for (int j = 0; j < 4; j++) acc[i][j] = 0ULL;

    for (int i = 0; i < 16; i++) {
        if (i < 13)      cp_wait<2>();
        else if (i < 15) cp_wait<1>();
        else             cp_wait<0>();
        __syncthreads();
        const float* Ap = Asm + (i & 3) * 2304;
        const float* Bp = Bsm + (i & 3) * 1024;
#pragma unroll
        for (int kk2 = 0; kk2 < 16; kk2++) {
            ull a0 = *(const ull*)(Ap + b0 * 36 + kk2 * 2);
            ull a1 = *(const ull*)(Ap + b1 * 36 + kk2 * 2);
            ulonglong2 wA = *(const ulonglong2*)(Bp + kk2 * 64 + tx * 8);
            ulonglong2 wB = *(const ulonglong2*)(Bp + kk2 * 64 + tx * 8 + 4);
            fma2(acc[0][0], a0, wA.x); fma2(acc[0][1], a0, wA.y);
            fma2(acc[0][2], a0, wB.x); fma2(acc[0][3], a0, wB.y);
            fma2(acc[1][0], a1, wA.x); fma2(acc[1][1], a1, wA.y);
            fma2(acc[1][2], a1, wB.x); fma2(acc[1][3], a1, wB.y);
        }
        if (i + 3 < 16) { LS_STAGE((i + 3) & 3, (i + 3) * 32); cp_commit(); }
    }
#undef LS_STAGE

    // epilogue: fold k-even/odd partials, gates, state update
#pragma unroll
    for (int i = 0; i < 2; i++) {
        int b = (i == 0) ? b0 : b1;
        float4 pv = (i == 0) ? pv0 : pv1;
        float cv  = (i == 0) ? cv0 : cv1;
        float2 e0 = unpack2(acc[i][0]);
        float2 e1 = unpack2(acc[i][1]);
        float2 e2 = unpack2(acc[i][2]);
        float2 e3 = unpack2(acc[i][3]);
        float gi = e0.x + e0.y + pv.x + bb4.x;
        float gf = e1.x + e1.y + pv.y + bb4.y;
        float go = e2.x + e2.y + pv.z + bb4.z;
        float gg = e3.x + e3.y + pv.w + bb4.w;
        float ig = 1.f / (1.f + expf(-gi));
        float fg = 1.f / (1.f + expf(-gf));
        float og = 1.f / (1.f + expf(-go));
        float gt = tanhf(gg);
        float c = fg * cv + ig * gt;
        float h = og * tanhf(c);
        cst[b * UU + u] = c;
        hout[b * UU + u] = h;
        outp[((size_t)t * BB + b) * ostride + u] = h;
        if (outT) outT[(size_t)u * MTOT + t * BB + b] = h;
    }
}

// ---------------- span feature gather ----------------------------------------
__global__ void build_hi(const int* __restrict__ sl, const int* __restrict__ sr,
                         const int* __restrict__ ll, const int* __restrict__ lr) {
    int idx = blockIdx.x * blockDim.x + threadIdx.x;
    const int NS = BB * 4 * 2048;
    int b, s, c, le, ri;
    float* dst;
    if (idx < NS) {
        b = idx / (4 * 2048); int r = idx - b * (4 * 2048);
        s = r / 2048; c = r - s * 2048;
        le = sl[b * 4 + s]; ri = sr[b * 4 + s];
        dst = g_hi_s + (size_t)b * 8192 + s * 2048 + c;
    } else {
        int j = idx - NS;
        b = j / (3 * 2048); int r = j - b * (3 * 2048);
        s = r / 2048; c = r - s * 2048;
        le = ll[b * 3 + s]; ri = lr[b * 3 + s];
        dst = g_hi_l + (size_t)b * 6144 + s * 2048 + c;
    }
    float v;
    if (c < 512) {
        v = g_in2[((size_t)ri * BB + b) * 1024 + c] - g_in2[((size_t)(le - 1) * BB + b) * 1024 + c];
    } else if (c < 1024) {
        int u = c - 512;
        v = g_fwd2[((size_t)ri * BB + b) * UU + u] - g_fwd2[((size_t)(le - 1) * BB + b) * UU + u];
    } else if (c < 1536) {
        int u = c - 1024;
        v = g_in2[((size_t)le * BB + b) * 1024 + 512 + u] - g_in2[((size_t)(ri + 1) * BB + b) * 1024 + 512 + u];
    } else {
        int u = c - 1536;
        v = g_back2[((size_t)le * BB + b) * UU + u] - g_back2[((size_t)(ri + 1) * BB + b) * UU + u];
    }
    *dst = v;
}

// ---------------- span hidden GEMM: M=64, split-K into partial planes --------
__global__ void __launch_bounds__(256) span_gemm(
    const float* __restrict__ A, int lda, const float* __restrict__ B,
    float* __restrict__ Cpart) {
    __shared__ float AsT[16][68];
    __shared__ float Bs[16][68];
    int n0 = blockIdx.x * 64;
    int kbase = blockIdx.y * 512;
    int tid = threadIdx.x;
    int tx = tid & 15, ty = tid >> 4;
    float acc[4][4] = {{0}};
    int ab = tid >> 2, aseg = (tid & 3) * 4;
    int bkk = tid >> 4, bnn = (tid & 15) * 4;
    for (int k0 = kbase; k0 < kbase + 512; k0 += 16) {
        float4 av = *(const float4*)(A + (size_t)ab * lda + k0 + aseg);
        float4 wv = *(const float4*)(B + (size_t)(k0 + bkk) * HD + n0 + bnn);
        __syncthreads();
        AsT[aseg + 0][ab] = av.x; AsT[aseg + 1][ab] = av.y;
        AsT[aseg + 2][ab] = av.z; AsT[aseg + 3][ab] = av.w;
        *(float4*)&Bs[bkk][bnn] = wv;
        __syncthreads();
#pragma unroll
        for (int kk = 0; kk < 16; kk++) {
            float4 a = *(float4*)&AsT[kk][ty * 4];
            float4 w = *(float4*)&Bs[kk][tx * 4];
            float aa[4] = {a.x, a.y, a.z, a.w};
            float ww[4] = {w.x, w.y, w.z, w.w};
#pragma unroll
            for (int i = 0; i < 4; i++)
#pragma unroll
                for (int j = 0; j < 4; j++) acc[i][j] += aa[i] * ww[j];
        }
    }
#pragma unroll
    for (int i = 0; i < 4; i++) {
        int b = ty * 4 + i;
        float4 v = {acc[i][0], acc[i][1], acc[i][2], acc[i][3]};
        *(float4*)(Cpart + ((size_t)blockIdx.y * BB + b) * HD + n0 + tx * 4) = v;
    }
}

__global__ void reduce_relu(const float* __restrict__ part, int nch,
                            const float* __restrict__ bias, float* __restrict__ outh) {
    int idx = blockIdx.x * blockDim.x + threadIdx.x;
    int n = idx & (HD - 1);
    float s = bias[n];
    for (int ch = 0; ch < nch; ch++) s += part[(size_t)ch * BB * HD + idx];
    outh[idx] = fmaxf(s, 0.f);
}

// ---------------- output heads ------------------------------------------------
__global__ void out_heads(const float* __restrict__ soW, const float* __restrict__ sob,
                          const float* __restrict__ loW, const float* __restrict__ lob,
                          float* __restrict__ out) {
    __shared__ float s1[HD], s2[HD];
    int b = blockIdx.x, tid = threadIdx.x;
    for (int i = tid; i < HD; i += blockDim.x) {
        s1[i] = g_hs[b * HD + i];
        s2[i] = g_hl[b * HD + i];
    }
    __syncthreads();
    if (tid < 2) {
        float s = sob[tid];
        for (int k = 0; k < HD; k++) s += s1[k] * soW[k * 2 + tid];
        out[b * 2 + tid] = s;
    } else if (tid < 34) {
        int j = tid - 2;
        float s = lob[j];
        for (int k = 0; k < HD; k++) s += s2[k] * loW[k * 32 + j];
        out[128 + b * 32 + j] = s;
    }
}

// ---------------- host driver --------------------------------------------------
static float* sym(const void* symbol) {
    void* p = nullptr;
    cudaGetSymbolAddress(&p, symbol);
    return (float*)p;
}

extern "C" void kernel_launch(void* const* d_in, const int* in_sizes, int n_in,
                              void* d_out, int out_size) {
    const float* word_emb = (const float*)d_in[0];
    const float* tag_emb  = (const float*)d_in[1];
    const float* l1f_W = (const float*)d_in[2];
    const float* l1f_b = (const float*)d_in[3];
    const float* l1f_c0 = (const float*)d_in[4];
    const float* l1b_W = (const float*)d_in[5];
    const float* l1b_b = (const float*)d_in[6];
    const float* l1b_c0 = (const float*)d_in[7];
    const float* l2f_W = (const float*)d_in[8];
    const float* l2f_b = (const float*)d_in[9];
    const float* l2f_c0 = (const float*)d_in[10];
    const float* l2b_W = (const float*)d_in[11];
    const float* l2b_b = (const float*)d_in[12];
    const float* l2b_c0 = (const float*)d_in[13];
    const float* sh_W = (const float*)d_in[14];
    const float* sh_b = (const float*)d_in[15];
    const float* so_W = (const float*)d_in[16];
    const float* so_b = (const float*)d_in[17];
    const float* lh_W = (const float*)d_in[18];
    const float* lh_b = (const float*)d_in[19];
    const float* lo_W = (const float*)d_in[20];
    const float* lo_b = (const float*)d_in[21];
    const int* word_inds = (const int*)d_in[22];
    const int* tag_inds  = (const int*)d_in[23];
    const int* s_lefts  = (const int*)d_in[24];
    const int* s_rights = (const int*)d_in[25];
    const int* l_lefts  = (const int*)d_in[26];
    const int* l_rights = (const int*)d_in[27];
    float* out = (float*)d_out;

    float* p_sent  = sym(g_sent);
    float* p_sentT = sym(g_sentT);
    float* p_preF  = sym(g_preF);
    float* p_preB  = sym(g_preB);
    float* p_in2   = sym(g_in2);
    float* p_in2T  = sym(g_in2T);
    float* p_fwd2  = sym(g_fwd2);
    float* p_back2 = sym(g_back2);
    float* p_Wx1f = sym(g_Wx1f); float* p_Wx1b = sym(g_Wx1b);
    float* p_Wh1f = sym(g_Wh1f); float* p_Wh1b = sym(g_Wh1b);
    float* p_Wx2f = sym(g_Wx2f); float* p_Wx2b = sym(g_Wx2b);
    float* p_Wh2f = sym(g_Wh2f); float* p_Wh2b = sym(g_Wh2b);
    float* p_bv1f = sym(g_bv1f); float* p_bv1b = sym(g_bv1b);
    float* p_bv2f = sym(g_bv2f); float* p_bv2b = sym(g_bv2b);
    float* p_hFa = sym(g_hFa); float* p_hFb = sym(g_hFb);
    float* p_hBa = sym(g_hBa); float* p_hBb = sym(g_hBb);
    float* p_hi_s = sym(g_hi_s); float* p_hi_l = sym(g_hi_l);
    float* p_part_s = sym(g_part_s); float* p_part_l = sym(g_part_l);
    float* p_hs = sym(g_hs); float* p_hl = sym(g_hl);

    const int LSTM_SMEM = (4 * 2304 + 4 * 1024) * 4;   // 53,248 B
    static int smem_set = 0;
    if (!smem_set) {
        cudaFuncSetAttribute(lstm_step, cudaFuncAttributeMaxDynamicSharedMemorySize,
                             LSTM_SMEM);
        smem_set = 1;
    }

    // 1) pack weights
    pack_lstm<<<2048, 256>>>(l1f_W, l1f_b, p_Wx1f, p_Wh1f, p_bv1f, SENT_D);
    pack_lstm<<<2048, 256>>>(l1b_W, l1b_b, p_Wx1b, p_Wh1b, p_bv1b, SENT_D);
    pack_lstm<<<4096, 256>>>(l2f_W, l2f_b, p_Wx2f, p_Wh2f, p_bv2f, 1024);
    pack_lstm<<<4096, 256>>>(l2b_W, l2b_b, p_Wx2b, p_Wh2b, p_bv2b, 1024);

    // 2) embeddings + transpose for GEMM A operand
    embed_kernel<<<(MTOT * SENT_D) / 256, 256>>>(word_emb, tag_emb, word_inds, tag_inds);
    transpose32<<<dim3(SENT_D / 32, MTOT / 32), dim3(32, 8)>>>(p_sent, p_sentT, MTOT, SENT_D);

    // 3) layer-1 input projections (16384 x 320 x 2048), A transposed
    dim3 gpre(G4 / 128, MTOT / 128);
    sgemm_nt<<<gpre, 256>>>(p_sentT, p_Wx1f, p_preF, SENT_D, MTOT, G4, G4);
    sgemm_nt<<<gpre, 256>>>(p_sentT, p_Wx1b, p_preB, SENT_D, MTOT, G4, G4);

    // 4) layer-1 recurrence (writes in2 + in2T)
    init_states<<<(BB * UU) / 256, 256>>>(l1f_c0, l1b_c0);
    for (int s = 0; s < T_LEN; s++) {
        const float* hinF = (s & 1) ? p_hFb : p_hFa;
        float* houtF      = (s & 1) ? p_hFa : p_hFb;
        const float* hinB = (s & 1) ? p_hBb : p_hBa;
        float* houtB      = (s & 1) ? p_hBa : p_hBb;
        lstm_step<<<128, 256, LSTM_SMEM>>>(
            p_preF, p_preB, p_Wh1f, p_Wh1b, p_bv1f, p_bv1b,
            hinF, houtF, hinB, houtB,
            p_in2, p_in2 + 512, p_in2T, p_in2T + (size_t)512 * MTOT,
            1024, s, T_LEN - 1 - s);
    }

    // 5) layer-2 input projections (16384 x 1024 x 2048), A = in2T
    sgemm_nt<<<gpre, 256>>>(p_in2T, p_Wx2f, p_preF, 1024, MTOT, G4, G4);
    sgemm_nt<<<gpre, 256>>>(p_in2T, p_Wx2b, p_preB, 1024, MTOT, G4, G4);

    // 6) layer-2 recurrence (no transposed output needed)
    init_states<<<(BB * UU) / 256, 256>>>(l2f_c0, l2b_c0);
    for (int s = 0; s < T_LEN; s++) {
        const float* hinF = (s & 1) ? p_hFb : p_hFa;
        float* houtF      = (s & 1) ? p_hFa : p_hFb;
        const float* hinB = (s & 1) ? p_hBb : p_hBa;
        float* houtB      = (s & 1) ? p_hBa : p_hBb;
        lstm_step<<<128, 256, LSTM_SMEM>>>(
            p_preF, p_preB, p_Wh2f, p_Wh2b, p_bv2f, p_bv2b,
            hinF, houtF, hinB, houtB,
            p_fwd2, p_back2, (float*)nullptr, (float*)nullptr,
            UU, s, T_LEN - 1 - s);
    }

    // 7) span features
    build_hi<<<(BB * 7 * 2048) / 256, 256>>>(s_lefts, s_rights, l_lefts, l_rights);

    // 8) span hidden layers
    span_gemm<<<dim3(HD / 64, 16), 256>>>(p_hi_s, 8192, sh_W, p_part_s);
    span_gemm<<<dim3(HD / 64, 12), 256>>>(p_hi_l, 6144, lh_W, p_part_l);
    reduce_relu<<<(BB * HD) / 256, 256>>>(p_part_s, 16, sh_b, p_hs);
    reduce_relu<<<(BB * HD) / 256, 256>>>(p_part_l, 12, lh_b, p_hl);

    // 9) output heads
    out_heads<<<BB, 128>>>(so_W, so_b, lo_W, lo_b, out);
}

// round 9
// speedup vs baseline: 1.4445x; 1.2609x over previous
#include <cuda_runtime.h>
#include <math.h>
#include <stdint.h>

#define T_LEN 256
#define BB 64
#define SENT_D 320
#define UU 512
#define G4 2048
#define HD 1024
#define MTOT (T_LEN * BB)          // 16384

typedef unsigned long long ull;

// ---------------- packed f32x2 + cp.async helpers ----------------------------
__device__ __forceinline__ void fma2(ull& d, ull a, ull b) {
    asm("fma.rn.f32x2 %0, %1, %2, %0;" : "+l"(d) : "l"(a), "l"(b));
}
__device__ __forceinline__ ull dup2(float x) {
    ull r;
    asm("mov.b64 %0, {%1, %1};" : "=l"(r) : "f"(x));
    return r;
}
__device__ __forceinline__ float2 unpack2(ull v) {
    float2 r;
    asm("mov.b64 {%0, %1}, %2;" : "=f"(r.x), "=f"(r.y) : "l"(v));
    return r;
}
__device__ __forceinline__ void cp_async16(uint32_t saddr, const void* gptr) {
    asm volatile("cp.async.cg.shared.global [%0], [%1], 16;" :: "r"(saddr), "l"(gptr));
}
__device__ __forceinline__ void cp_commit() {
    asm volatile("cp.async.commit_group;" ::: "memory");
}
template<int N> __device__ __forceinline__ void cp_wait() {
    asm volatile("cp.async.wait_group %0;" :: "n"(N) : "memory");
}

// ---------------- scratch (device globals; no allocs allowed) ----------------
__device__ float g_sent[MTOT * SENT_D];
__device__ float g_sentT[SENT_D * MTOT];                 // [320][16384]
__device__ float g_preF[(size_t)MTOT * G4];
__device__ float g_preB[(size_t)MTOT * G4];
__device__ float g_in2[(size_t)MTOT * 1024];             // [t][b][c]
__device__ float g_in2T[(size_t)1024 * MTOT];            // [c][t*64+b]
__device__ float g_fwd2[(size_t)MTOT * UU];
__device__ float g_back2[(size_t)MTOT * UU];

__device__ float g_Wx1f[SENT_D * G4], g_Wx1b[SENT_D * G4];
__device__ float g_Wh1f[UU * G4],     g_Wh1b[UU * G4];   // k-paired + plane layout
__device__ float g_Wx2f[1024 * G4],   g_Wx2b[1024 * G4];
__device__ float g_Wh2f[UU * G4],     g_Wh2b[UU * G4];
__device__ float g_bv1f[G4], g_bv1b[G4], g_bv2f[G4], g_bv2b[G4];

__device__ float g_hFa[BB * UU], g_hFb[BB * UU];
__device__ float g_hBa[BB * UU], g_hBb[BB * UU];
__device__ float g_cF[BB * UU],  g_cB[BB * UU];

__device__ float g_hi_s[BB * 8192];
__device__ float g_hi_l[BB * 6144];
__device__ float g_part_s[16 * BB * HD];
__device__ float g_part_l[12 * BB * HD];
__device__ float g_hs[BB * HD], g_hl[BB * HD];

// ---------------- weight packing ----------------------------------------------
// Wx: column n = u*4 + k (gate-interleaved).
// Wh: k-pair-interleaved + per-32-gate-tile plane layout:
//   row = kd>>1 (4096 floats); within tile (n>>5):
//   col = (n>>5)*64 + (j>>1)*32 + txx*4 + ((j&1)<<1) + (kd&1),
//   where loc = n&31, txx = loc>>2, j = loc&3.
__global__ void pack_lstm(const float* __restrict__ W, const float* __restrict__ b,
                          float* __restrict__ Wx, float* __restrict__ Wh,
                          float* __restrict__ bv, int din) {
    int total = 4 * (din + UU) * UU;
    int stride = gridDim.x * blockDim.x;
    for (int idx = blockIdx.x * blockDim.x + threadIdx.x; idx < total; idx += stride) {
        int k = idx / ((din + UU) * UU);
        int rem = idx - k * ((din + UU) * UU);
        int d = rem / UU;
        int u = rem - d * UU;
        float v = W[idx];
        int n = u * 4 + k;
        if (d < din) {
            Wx[(size_t)d * G4 + n] = v;
        } else {
            int kd = d - din;
            int tile = n >> 5, loc = n & 31;
            int txx = loc >> 2, j = loc & 3;
            int col = tile * 64 + (j >> 1) * 32 + txx * 4 + ((j & 1) << 1) + (kd & 1);
            Wh[(size_t)(kd >> 1) * 4096 + col] = v;
        }
    }
    for (int i = blockIdx.x * blockDim.x + threadIdx.x; i < G4; i += stride) {
        int k = i & 3, u = i >> 2;
        bv[i] = b[k * UU + u];
    }
}

// ---------------- embedding gather + concat ----------------------------------
__global__ void embed_kernel(const float* __restrict__ we, const float* __restrict__ te,
                             const int* __restrict__ wi, const int* __restrict__ ti) {
    int idx = blockIdx.x * blockDim.x + threadIdx.x;
    int tb = idx / SENT_D;
    int j = idx - tb * SENT_D;
    float v;
    if (j < 256) v = we[(size_t)wi[tb] * 256 + j];
    else         v = te[(size_t)ti[tb] * 64 + (j - 256)];
    g_sent[idx] = v;
}

// ---------------- tiled transpose: dst[c][r] = src[r][c] ----------------------
__global__ void transpose32(const float* __restrict__ src, float* __restrict__ dst,
                            int R, int Cc) {
    __shared__ float tl[32][33];
    int c0 = blockIdx.x * 32, r0 = blockIdx.y * 32;
    int tx = threadIdx.x, ty = threadIdx.y;   // 32 x 8
#pragma unroll
    for (int i = 0; i < 32; i += 8)
        tl[ty + i][tx] = src[(size_t)(r0 + ty + i) * Cc + c0 + tx];
    __syncthreads();
#pragma unroll
    for (int i = 0; i < 32; i += 8)
        dst[(size_t)(c0 + ty + i) * R + r0 + tx] = tl[tx][ty + i];
}

// ---------------- LSTM state init --------------------------------------------
__global__ void init_states(const float* __restrict__ c0f, const float* __restrict__ c0b) {
    int idx = blockIdx.x * blockDim.x + threadIdx.x;   // B*U = 32768
    int u = idx & (UU - 1);
    float cf = c0f[u], cb = c0b[u];
    g_cF[idx] = cf;  g_hFa[idx] = tanhf(cf);
    g_cB[idx] = cb;  g_hBa[idx] = tanhf(cb);
}

// ---------------- big GEMM: C = AT^T @ B, cp.async double-buffered ------------
__global__ void __launch_bounds__(256) sgemm_nt(
    const float* __restrict__ AT, const float* __restrict__ B, float* __restrict__ C,
    int K, int ldat, int ldb, int ldc) {
    __shared__ float As[2][16 * 132];
    __shared__ float Bs[2][16 * 132];
    int m0 = blockIdx.y * 128, n0 = blockIdx.x * 128;
    int tid = threadIdx.x;
    int tx = tid & 15, ty = tid >> 4;
    uint32_t as0 = (uint32_t)__cvta_generic_to_shared(&As[0][0]);
    uint32_t bs0 = (uint32_t)__cvta_generic_to_shared(&Bs[0][0]);
    int akk = tid >> 5, aoff = (tid & 31) * 4;

    ull acc[4][8];
#pragma unroll
    for (int p = 0; p < 4; p++)
#pragma unroll
        for (int j = 0; j < 8; j++) acc[p][j] = 0ULL;

#define SG_STAGE(pp, kk0) do { \
        cp_async16(as0 + (uint32_t)(((pp) * 2112 + akk * 132 + aoff) * 4), \
                   AT + (size_t)((kk0) + akk) * ldat + m0 + aoff); \
        cp_async16(as0 + (uint32_t)(((pp) * 2112 + (akk + 8) * 132 + aoff) * 4), \
                   AT + (size_t)((kk0) + akk + 8) * ldat + m0 + aoff); \
        cp_async16(bs0 + (uint32_t)(((pp) * 2112 + akk * 132 + aoff) * 4), \
                   B + (size_t)((kk0) + akk) * ldb + n0 + aoff); \
        cp_async16(bs0 + (uint32_t)(((pp) * 2112 + (akk + 8) * 132 + aoff) * 4), \
                   B + (size_t)((kk0) + akk + 8) * ldb + n0 + aoff); \
    } while (0)

    SG_STAGE(0, 0);
    cp_commit();

    int p = 0;
    for (int k0 = 0; k0 < K; k0 += 16, p ^= 1) {
        if (k0 + 16 < K) {
            SG_STAGE(p ^ 1, k0 + 16);
            cp_commit();
            cp_wait<1>();
        } else {
            cp_wait<0>();
        }
        __syncthreads();
        const float* Ap = &As[p][0];
        const float* Bp = &Bs[p][0];
#pragma unroll
        for (int kk = 0; kk < 16; kk++) {
            ull ap[4];
#pragma unroll
            for (int q = 0; q < 4; q++)
                ap[q] = *(const ull*)(Ap + kk * 132 + ty * 8 + 2 * q);
            float4 bv0 = *(const float4*)(Bp + kk * 132 + tx * 8);
            float4 bv1 = *(const float4*)(Bp + kk * 132 + tx * 8 + 4);
            ull bd[8] = {dup2(bv0.x), dup2(bv0.y), dup2(bv0.z), dup2(bv0.w),
                         dup2(bv1.x), dup2(bv1.y), dup2(bv1.z), dup2(bv1.w)};
#pragma unroll
            for (int q = 0; q < 4; q++)
#pragma unroll
                for (int j = 0; j < 8; j++) fma2(acc[q][j], ap[q], bd[j]);
        }
        __syncthreads();
    }
#undef SG_STAGE

#pragma unroll
    for (int q = 0; q < 4; q++) {
        float v0[8], v1[8];
#pragma unroll
        for (int j = 0; j < 8; j++) {
            float2 t = unpack2(acc[q][j]);
            v0[j] = t.x; v1[j] = t.y;
        }
        float* c0 = C + (size_t)(m0 + ty * 8 + 2 * q) * ldc + n0 + tx * 8;
        float* c1 = c0 + ldc;
        *(float4*)c0 = make_float4(v0[0], v0[1], v0[2], v0[3]);
        *(float4*)(c0 + 4) = make_float4(v0[4], v0[5], v0[6], v0[7]);
        *(float4*)c1 = make_float4(v1[0], v1[1], v1[2], v1[3]);
        *(float4*)(c1 + 4) = make_float4(v1[4], v1[5], v1[6], v1[7]);
    }
}

// ---------------- one recurrent step: 128 CTAs x 128 thr ---------------------
// blk>>6 = dir, blk&63 = 32-wide gate tile (8 units). Thread tile 4b x 4g
// (one unit's 4 gates). tx = tid>>4 (unit in tile), ty = tid&15 (b-group).
// A smem: permuted rows perm(b) = (b&3)*16 + (b>>2), stride 36 — warp A loads
// are 16-addr/2-phase with 2-way broadcast; W smem: plane-split rows, warp W
// loads are 2-addr contiguous with 16-way broadcast. cp.async 4-stage ring.
__global__ void __launch_bounds__(128) lstm_step(
    const float* __restrict__ preF, const float* __restrict__ preB,
    const float* __restrict__ WpF,  const float* __restrict__ WpB,
    const float* __restrict__ bvF,  const float* __restrict__ bvB,
    const float* __restrict__ hinF, float* __restrict__ houtF,
    const float* __restrict__ hinB, float* __restrict__ houtB,
    float* __restrict__ outF, float* __restrict__ outB,
    float* __restrict__ outTF, float* __restrict__ outTB,
    int ostride, int tF, int tB) {
    extern __shared__ float sm[];
    float* Asm = sm;                    // 4 stages x 64*36 floats
    float* Bsm = sm + 4 * 2304;         // 4 stages x 16*64 floats

    int blk = blockIdx.x;
    int dir = blk >> 6;
    int nb  = blk & 63;
    int n0  = nb * 32;

    const float* pre = dir ? preB : preF;
    const float* Wp  = dir ? WpB : WpF;
    const float* bv  = dir ? bvB : bvF;
    const float* hin = dir ? hinB : hinF;
    float* hout = dir ? houtB : houtF;
    float* cst  = dir ? g_cB : g_cF;
    float* outp = dir ? outB : outF;
    float* outT = dir ? outTB : outTF;
    int t = dir ? tB : tF;

    int tid = threadIdx.x;
    int tx = tid >> 4;            // 0..7 : unit within tile
    int ty = tid & 15;            // 0..15: b-group of 4
    int b0 = ty * 4;
    int u = nb * 8 + tx;

    uint32_t asb = (uint32_t)__cvta_generic_to_shared(Asm);
    uint32_t bsb = (uint32_t)__cvta_generic_to_shared(Bsm);

    // early independent loads (latency hides under the k-loop)
    float4 pv[4];
    float cv[4];
#pragma unroll
    for (int r = 0; r < 4; r++) {
        pv[r] = *(const float4*)(pre + ((size_t)t * BB + b0 + r) * G4 + n0 + tx * 4);
        cv[r] = cst[(b0 + r) * UU + u];
    }
    float4 bb4 = *(const float4*)(bv + n0 + tx * 4);

    // staging assignments: A row sa_row (2 threads/row, 16 floats each),
    // stored at permuted physical row; W row sw_row (8 threads/row, 8 floats).
    int sa_row = tid >> 1, sa_off = (tid & 1) * 16;
    int sa_prow = (sa_row & 3) * 16 + (sa_row >> 2);
    int sw_row = tid >> 3, sw_off = (tid & 7) * 8;

#define LS9(st, k0) do { \
        _Pragma("unroll") \
        for (int j = 0; j < 4; j++) \
            cp_async16(asb + (uint32_t)((((st) * 2304) + sa_prow * 36 + sa_off + j * 4) * 4), \
                       hin + sa_row * UU + (k0) + sa_off + j * 4); \
        cp_async16(bsb + (uint32_t)((((st) * 1024) + sw_row * 64 + sw_off) * 4), \
                   Wp + (size_t)(((k0) >> 1) + sw_row) * 4096 + nb * 64 + sw_off); \
        cp_async16(bsb + (uint32_t)((((st) * 1024) + sw_row * 64 + sw_off + 4) * 4), \
                   Wp + (size_t)(((k0) >> 1) + sw_row) * 4096 + nb * 64 + sw_off + 4); \
    } while (0)

    LS9(0, 0);  cp_commit();
    LS9(1, 32); cp_commit();
    LS9(2, 64); cp_commit();

    ull acc[4][4];
#pragma unroll
    for (int r = 0; r < 4; r++)
#pragma unroll
        for (int j = 0; j < 4; j++) acc[r][j] = 0ULL;

    for (int i = 0; i < 16; i++) {
        if (i < 13)      cp_wait<2>();
        else if (i < 15) cp_wait<1>();
        else             cp_wait<0>();
        __syncthreads();
        const float* Ap = Asm + (i & 3) * 2304;
        const float* Bp = Bsm + (i & 3) * 1024;
#pragma unroll
        for (int kk4 = 0; kk4 < 8; kk4++) {
            ulonglong2 a2[4];
#pragma unroll
            for (int r = 0; r < 4; r++)
                a2[r] = *(const ulonglong2*)(Ap + (r * 16 + ty) * 36 + kk4 * 4);
#pragma unroll
            for (int h = 0; h < 2; h++) {
                int kk2 = kk4 * 2 + h;
                ulonglong2 w01 = *(const ulonglong2*)(Bp + kk2 * 64 + tx * 4);
                ulonglong2 w23 = *(const ulonglong2*)(Bp + kk2 * 64 + 32 + tx * 4);
#pragma unroll
                for (int r = 0; r < 4; r++) {
                    ull a = h ? a2[r].y : a2[r].x;
                    fma2(acc[r][0], a, w01.x);
                    fma2(acc[r][1], a, w01.y);
                    fma2(acc[r][2], a, w23.x);
                    fma2(acc[r][3], a, w23.y);
                }
            }
        }
        if (i + 3 < 16) { LS9((i + 3) & 3, (i + 3) * 32); cp_commit(); }
    }
#undef LS9

    // epilogue: fold k-even/odd partials, gates, state update
#pragma unroll
    for (int r = 0; r < 4; r++) {
        int b = b0 + r;
        float2 e0 = unpack2(acc[r][0]);
        float2 e1 = unpack2(acc[r][1]);
        float2 e2 = unpack2(acc[r][2]);
        float2 e3 = unpack2(acc[r][3]);
        float gi = e0.x + e0.y + pv[r].x + bb4.x;
        float gf = e1.x + e1.y + pv[r].y + bb4.y;
        float go = e2.x + e2.y + pv[r].z + bb4.z;
        float gg = e3.x + e3.y + pv[r].w + bb4.w;
        float ig = 1.f / (1.f + expf(-gi));
        float fg = 1.f / (1.f + expf(-gf));
        float og = 1.f / (1.f + expf(-go));
        float gt = tanhf(gg);
        float c = fg * cv[r] + ig * gt;
        float h = og * tanhf(c);
        cst[b * UU + u] = c;
        hout[b * UU + u] = h;
        outp[((size_t)t * BB + b) * ostride + u] = h;
        if (outT) outT[(size_t)u * MTOT + t * BB + b] = h;
    }
}

// ---------------- span feature gather ----------------------------------------
__global__ void build_hi(const int* __restrict__ sl, const int* __restrict__ sr,
                         const int* __restrict__ ll, const int* __restrict__ lr) {
    int idx = blockIdx.x * blockDim.x + threadIdx.x;
    const int NS = BB * 4 * 2048;
    int b, s, c, le, ri;
    float* dst;
    if (idx < NS) {
        b = idx / (4 * 2048); int r = idx - b * (4 * 2048);
        s = r / 2048; c = r - s * 2048;
        le = sl[b * 4 + s]; ri = sr[b * 4 + s];
        dst = g_hi_s + (size_t)b * 8192 + s * 2048 + c;
    } else {
        int j = idx - NS;
        b = j / (3 * 2048); int r = j - b * (3 * 2048);
        s = r / 2048; c = r - s * 2048;
        le = ll[b * 3 + s]; ri = lr[b * 3 + s];
        dst = g_hi_l + (size_t)b * 6144 + s * 2048 + c;
    }
    float v;
    if (c < 512) {
        v = g_in2[((size_t)ri * BB + b) * 1024 + c] - g_in2[((size_t)(le - 1) * BB + b) * 1024 + c];
    } else if (c < 1024) {
        int u = c - 512;
        v = g_fwd2[((size_t)ri * BB + b) * UU + u] - g_fwd2[((size_t)(le - 1) * BB + b) * UU + u];
    } else if (c < 1536) {
        int u = c - 1024;
        v = g_in2[((size_t)le * BB + b) * 1024 + 512 + u] - g_in2[((size_t)(ri + 1) * BB + b) * 1024 + 512 + u];
    } else {
        int u = c - 1536;
        v = g_back2[((size_t)le * BB + b) * UU + u] - g_back2[((size_t)(ri + 1) * BB + b) * UU + u];
    }
    *dst = v;
}

// ---------------- span hidden GEMM: M=64, split-K into partial planes --------
__global__ void __launch_bounds__(256) span_gemm(
    const float* __restrict__ A, int lda, const float* __restrict__ B,
    float* __restrict__ Cpart) {
    __shared__ float AsT[16][68];
    __shared__ float Bs[16][68];
    int n0 = blockIdx.x * 64;
    int kbase = blockIdx.y * 512;
    int tid = threadIdx.x;
    int tx = tid & 15, ty = tid >> 4;
    float acc[4][4] = {{0}};
    int ab = tid >> 2, aseg = (tid & 3) * 4;
    int bkk = tid >> 4, bnn = (tid & 15) * 4;
    for (int k0 = kbase; k0 < kbase + 512; k0 += 16) {
        float4 av = *(const float4*)(A + (size_t)ab * lda + k0 + aseg);
        float4 wv = *(const float4*)(B + (size_t)(k0 + bkk) * HD + n0 + bnn);
        __syncthreads();
        AsT[aseg + 0][ab] = av.x; AsT[aseg + 1][ab] = av.y;
        AsT[aseg + 2][ab] = av.z; AsT[aseg + 3][ab] = av.w;
        *(float4*)&Bs[bkk][bnn] = wv;
        __syncthreads();
#pragma unroll
        for (int kk = 0; kk < 16; kk++) {
            float4 a = *(float4*)&AsT[kk][ty * 4];
            float4 w = *(float4*)&Bs[kk][tx * 4];
            float aa[4] = {a.x, a.y, a.z, a.w};
            float ww[4] = {w.x, w.y, w.z, w.w};
#pragma unroll
            for (int i = 0; i < 4; i++)
#pragma unroll
                for (int j = 0; j < 4; j++) acc[i][j] += aa[i] * ww[j];
        }
    }
#pragma unroll
    for (int i = 0; i < 4; i++) {
        int b = ty * 4 + i;
        float4 v = {acc[i][0], acc[i][1], acc[i][2], acc[i][3]};
        *(float4*)(Cpart + ((size_t)blockIdx.y * BB + b) * HD + n0 + tx * 4) = v;
    }
}

__global__ void reduce_relu(const float* __restrict__ part, int nch,
                            const float* __restrict__ bias, float* __restrict__ outh) {
    int idx = blockIdx.x * blockDim.x + threadIdx.x;
    int n = idx & (HD - 1);
    float s = bias[n];
    for (int ch = 0; ch < nch; ch++) s += part[(size_t)ch * BB * HD + idx];
    outh[idx] = fmaxf(s, 0.f);
}

// ---------------- output heads ------------------------------------------------
__global__ void out_heads(const float* __restrict__ soW, const float* __restrict__ sob,
                          const float* __restrict__ loW, const float* __restrict__ lob,
                          float* __restrict__ out) {
    __shared__ float s1[HD], s2[HD];
    int b = blockIdx.x, tid = threadIdx.x;
    for (int i = tid; i < HD; i += blockDim.x) {
        s1[i] = g_hs[b * HD + i];
        s2[i] = g_hl[b * HD + i];
    }
    __syncthreads();
    if (tid < 2) {
        float s = sob[tid];
        for (int k = 0; k < HD; k++) s += s1[k] * soW[k * 2 + tid];
        out[b * 2 + tid] = s;
    } else if (tid < 34) {
        int j = tid - 2;
        float s = lob[j];
        for (int k = 0; k < HD; k++) s += s2[k] * loW[k * 32 + j];
        out[128 + b * 32 + j] = s;
    }
}

// ---------------- host driver --------------------------------------------------
static float* sym(const void* symbol) {
    void* p = nullptr;
    cudaGetSymbolAddress(&p, symbol);
    return (float*)p;
}

extern "C" void kernel_launch(void* const* d_in, const int* in_sizes, int n_in,
                              void* d_out, int out_size) {
    const float* word_emb = (const float*)d_in[0];
    const float* tag_emb  = (const float*)d_in[1];
    const float* l1f_W = (const float*)d_in[2];
    const float* l1f_b = (const float*)d_in[3];
    const float* l1f_c0 = (const float*)d_in[4];
    const float* l1b_W = (const float*)d_in[5];
    const float* l1b_b = (const float*)d_in[6];
    const float* l1b_c0 = (const float*)d_in[7];
    const float* l2f_W = (const float*)d_in[8];
    const float* l2f_b = (const float*)d_in[9];
    const float* l2f_c0 = (const float*)d_in[10];
    const float* l2b_W = (const float*)d_in[11];
    const float* l2b_b = (const float*)d_in[12];
    const float* l2b_c0 = (const float*)d_in[13];
    const float* sh_W = (const float*)d_in[14];
    const float* sh_b = (const float*)d_in[15];
    const float* so_W = (const float*)d_in[16];
    const float* so_b = (const float*)d_in[17];
    const float* lh_W = (const float*)d_in[18];
    const float* lh_b = (const float*)d_in[19];
    const float* lo_W = (const float*)d_in[20];
    const float* lo_b = (const float*)d_in[21];
    const int* word_inds = (const int*)d_in[22];
    const int* tag_inds  = (const int*)d_in[23];
    const int* s_lefts  = (const int*)d_in[24];
    const int* s_rights = (const int*)d_in[25];
    const int* l_lefts  = (const int*)d_in[26];
    const int* l_rights = (const int*)d_in[27];
    float* out = (float*)d_out;

    float* p_sent  = sym(g_sent);
    float* p_sentT = sym(g_sentT);
    float* p_preF  = sym(g_preF);
    float* p_preB  = sym(g_preB);
    float* p_in2   = sym(g_in2);
    float* p_in2T  = sym(g_in2T);
    float* p_fwd2  = sym(g_fwd2);
    float* p_back2 = sym(g_back2);
    float* p_Wx1f = sym(g_Wx1f); float* p_Wx1b = sym(g_Wx1b);
    float* p_Wh1f = sym(g_Wh1f); float* p_Wh1b = sym(g_Wh1b);
    float* p_Wx2f = sym(g_Wx2f); float* p_Wx2b = sym(g_Wx2b);
    float* p_Wh2f = sym(g_Wh2f); float* p_Wh2b = sym(g_Wh2b);
    float* p_bv1f = sym(g_bv1f); float* p_bv1b = sym(g_bv1b);
    float* p_bv2f = sym(g_bv2f); float* p_bv2b = sym(g_bv2b);
    float* p_hFa = sym(g_hFa); float* p_hFb = sym(g_hFb);
    float* p_hBa = sym(g_hBa); float* p_hBb = sym(g_hBb);
    float* p_hi_s = sym(g_hi_s); float* p_hi_l = sym(g_hi_l);
    float* p_part_s = sym(g_part_s); float* p_part_l = sym(g_part_l);
    float* p_hs = sym(g_hs); float* p_hl = sym(g_hl);

    const int LSTM_SMEM = (4 * 2304 + 4 * 1024) * 4;   // 53,248 B
    static int smem_set = 0;
    if (!smem_set) {
        cudaFuncSetAttribute(lstm_step, cudaFuncAttributeMaxDynamicSharedMemorySize,
                             LSTM_SMEM);
        smem_set = 1;
    }

    // 1) pack weights
    pack_lstm<<<2048, 256>>>(l1f_W, l1f_b, p_Wx1f, p_Wh1f, p_bv1f, SENT_D);
    pack_lstm<<<2048, 256>>>(l1b_W, l1b_b, p_Wx1b, p_Wh1b, p_bv1b, SENT_D);
    pack_lstm<<<4096, 256>>>(l2f_W, l2f_b, p_Wx2f, p_Wh2f, p_bv2f, 1024);
    pack_lstm<<<4096, 256>>>(l2b_W, l2b_b, p_Wx2b, p_Wh2b, p_bv2b, 1024);

    // 2) embeddings + transpose for GEMM A operand
    embed_kernel<<<(MTOT * SENT_D) / 256, 256>>>(word_emb, tag_emb, word_inds, tag_inds);
    transpose32<<<dim3(SENT_D / 32, MTOT / 32), dim3(32, 8)>>>(p_sent, p_sentT, MTOT, SENT_D);

    // 3) layer-1 input projections (16384 x 320 x 2048), A transposed
    dim3 gpre(G4 / 128, MTOT / 128);
    sgemm_nt<<<gpre, 256>>>(p_sentT, p_Wx1f, p_preF, SENT_D, MTOT, G4, G4);
    sgemm_nt<<<gpre, 256>>>(p_sentT, p_Wx1b, p_preB, SENT_D, MTOT, G4, G4);

    // 4) layer-1 recurrence (writes in2 + in2T)
    init_states<<<(BB * UU) / 256, 256>>>(l1f_c0, l1b_c0);
    for (int s = 0; s < T_LEN; s++) {
        const float* hinF = (s & 1) ? p_hFb : p_hFa;
        float* houtF      = (s & 1) ? p_hFa : p_hFb;
        const float* hinB = (s & 1) ? p_hBb : p_hBa;
        float* houtB      = (s & 1) ? p_hBa : p_hBb;
        lstm_step<<<128, 128, LSTM_SMEM>>>(
            p_preF, p_preB, p_Wh1f, p_Wh1b, p_bv1f, p_bv1b,
            hinF, houtF, hinB, houtB,
            p_in2, p_in2 + 512, p_in2T, p_in2T + (size_t)512 * MTOT,
            1024, s, T_LEN - 1 - s);
    }

    // 5) layer-2 input projections (16384 x 1024 x 2048), A = in2T
    sgemm_nt<<<gpre, 256>>>(p_in2T, p_Wx2f, p_preF, 1024, MTOT, G4, G4);
    sgemm_nt<<<gpre, 256>>>(p_in2T, p_Wx2b, p_preB, 1024, MTOT, G4, G4);

    // 6) layer-2 recurrence
    init_states<<<(BB * UU) / 256, 256>>>(l2f_c0, l2b_c0);
    for (int s = 0; s < T_LEN; s++) {
        const float* hinF = (s & 1) ? p_hFb : p_hFa;
        float* houtF      = (s & 1) ? p_hFa : p_hFb;
        const float* hinB = (s & 1) ? p_hBb : p_hBa;
        float* houtB      = (s & 1) ? p_hBa : p_hBb;
        lstm_step<<<128, 128, LSTM_SMEM>>>(
            p_preF, p_preB, p_Wh2f, p_Wh2b, p_bv2f, p_bv2b,
            hinF, houtF, hinB, houtB,
            p_fwd2, p_back2, (float*)nullptr, (float*)nullptr,
            UU, s, T_LEN - 1 - s);
    }

    // 7) span features
    build_hi<<<(BB * 7 * 2048) / 256, 256>>>(s_lefts, s_rights, l_lefts, l_rights);

    // 8) span hidden layers
    span_gemm<<<dim3(HD / 64, 16), 256>>>(p_hi_s, 8192, sh_W, p_part_s);
    span_gemm<<<dim3(HD / 64, 12), 256>>>(p_hi_l, 6144, lh_W, p_part_l);
    reduce_relu<<<(BB * HD) / 256, 256>>>(p_part_s, 16, sh_b, p_hs);
    reduce_relu<<<(BB * HD) / 256, 256>>>(p_part_l, 12, lh_b, p_hl);

    // 9) output heads
    out_heads<<<BB, 128>>>(so_W, so_b, lo_W, lo_b, out);
}

// round 12
// speedup vs baseline: 1.6864x; 1.1675x over previous
#include <cuda_runtime.h>
#include <math.h>
#include <stdint.h>

#define T_LEN 256
#define BB 64
#define SENT_D 320
#define UU 512
#define G4 2048
#define HD 1024
#define MTOT (T_LEN * BB)          // 16384
#define NCTA 128

typedef unsigned long long ull;

// ---------------- packed f32x2 + cp.async helpers ----------------------------
__device__ __forceinline__ void fma2(ull& d, ull a, ull b) {
    asm("fma.rn.f32x2 %0, %1, %2, %0;" : "+l"(d) : "l"(a), "l"(b));
}
__device__ __forceinline__ ull dup2(float x) {
    ull r;
    asm("mov.b64 %0, {%1, %1};" : "=l"(r) : "f"(x));
    return r;
}
__device__ __forceinline__ float2 unpack2(ull v) {
    float2 r;
    asm("mov.b64 {%0, %1}, %2;" : "=f"(r.x), "=f"(r.y) : "l"(v));
    return r;
}
__device__ __forceinline__ void cp_async16(uint32_t saddr, const void* gptr) {
    asm volatile("cp.async.cg.shared.global [%0], [%1], 16;" :: "r"(saddr), "l"(gptr));
}
__device__ __forceinline__ void cp_commit() {
    asm volatile("cp.async.commit_group;" ::: "memory");
}
template<int N> __device__ __forceinline__ void cp_wait() {
    asm volatile("cp.async.wait_group %0;" :: "n"(N) : "memory");
}

// ---------------- scratch (device globals; no allocs allowed) ----------------
__device__ float g_sent[MTOT * SENT_D];
__device__ float g_sentT[SENT_D * MTOT];
__device__ float g_preF[(size_t)MTOT * G4];
__device__ float g_preB[(size_t)MTOT * G4];
__device__ float g_in2[(size_t)MTOT * 1024];
__device__ float g_in2T[(size_t)1024 * MTOT];
__device__ float g_fwd2[(size_t)MTOT * UU];
__device__ float g_back2[(size_t)MTOT * UU];

__device__ float g_Wx1f[SENT_D * G4], g_Wx1b[SENT_D * G4];
__device__ float g_Wh1f[UU * G4],     g_Wh1b[UU * G4];   // k-paired + plane layout
__device__ float g_Wx2f[1024 * G4],   g_Wx2b[1024 * G4];
__device__ float g_Wh2f[UU * G4],     g_Wh2b[UU * G4];
__device__ float g_bv1f[G4], g_bv1b[G4], g_bv2f[G4], g_bv2b[G4];

__device__ float g_hFa[BB * UU], g_hFb[BB * UU];
__device__ float g_hBa[BB * UU], g_hBb[BB * UU];

__device__ float g_hi_s[BB * 8192];
__device__ float g_hi_l[BB * 6144];
__device__ float g_part_s[16 * BB * HD];
__device__ float g_part_l[12 * BB * HD];
__device__ float g_hs[BB * HD], g_hl[BB * HD];

__device__ unsigned g_sc;   // monotonic grid-barrier counter

// Grid barrier: every thread drains its own STG writes to the gpu coherence
// point BEFORE arriving, then t0 does release-add + acquire-poll.
__device__ __forceinline__ void gbar(unsigned target) {
    __syncthreads();
    asm volatile("fence.acq_rel.gpu;" ::: "memory");
    if (threadIdx.x == 0) {
        asm volatile("red.release.gpu.add.u32 [%0], 1;" :: "l"(&g_sc) : "memory");
        unsigned x;
        do {
            asm volatile("ld.acquire.gpu.u32 %0, [%1];" : "=r"(x) : "l"(&g_sc) : "memory");
        } while (x < target);
    }
    __syncthreads();
}

// ---------------- weight packing ----------------------------------------------
// Wx: column n = u*4 + k. Wh: k-paired + per-32-gate-tile plane layout.
__global__ void pack_lstm(const float* __restrict__ W, const float* __restrict__ b,
                          float* __restrict__ Wx, float* __restrict__ Wh,
                          float* __restrict__ bv, int din) {
    int total = 4 * (din + UU) * UU;
    int stride = gridDim.x * blockDim.x;
    for (int idx = blockIdx.x * blockDim.x + threadIdx.x; idx < total; idx += stride) {
        int k = idx / ((din + UU) * UU);
        int rem = idx - k * ((din + UU) * UU);
        int d = rem / UU;
        int u = rem - d * UU;
        float v = W[idx];
        int n = u * 4 + k;
        if (d < din) {
            Wx[(size_t)d * G4 + n] = v;
        } else {
            int kd = d - din;
            int tile = n >> 5, loc = n & 31;
            int txx = loc >> 2, j = loc & 3;
            int col = tile * 64 + (j >> 1) * 32 + txx * 4 + ((j & 1) << 1) + (kd & 1);
            Wh[(size_t)(kd >> 1) * 4096 + col] = v;
        }
    }
    for (int i = blockIdx.x * blockDim.x + threadIdx.x; i < G4; i += stride) {
        int k = i & 3, u = i >> 2;
        bv[i] = b[k * UU + u];
    }
}

// ---------------- embedding gather + concat ----------------------------------
__global__ void embed_kernel(const float* __restrict__ we, const float* __restrict__ te,
                             const int* __restrict__ wi, const int* __restrict__ ti) {
    int idx = blockIdx.x * blockDim.x + threadIdx.x;
    int tb = idx / SENT_D;
    int j = idx - tb * SENT_D;
    float v;
    if (j < 256) v = we[(size_t)wi[tb] * 256 + j];
    else         v = te[(size_t)ti[tb] * 64 + (j - 256)];
    g_sent[idx] = v;
}

// ---------------- tiled transpose --------------------------------------------
__global__ void transpose32(const float* __restrict__ src, float* __restrict__ dst,
                            int R, int Cc) {
    __shared__ float tl[32][33];
    int c0 = blockIdx.x * 32, r0 = blockIdx.y * 32;
    int tx = threadIdx.x, ty = threadIdx.y;   // 32 x 8
#pragma unroll
    for (int i = 0; i < 32; i += 8)
        tl[ty + i][tx] = src[(size_t)(r0 + ty + i) * Cc + c0 + tx];
    __syncthreads();
#pragma unroll
    for (int i = 0; i < 32; i += 8)
        dst[(size_t)(c0 + ty + i) * R + r0 + tx] = tl[tx][ty + i];
}

// ---------------- LSTM h-state init + barrier counter reset -------------------
__global__ void init_states(const float* __restrict__ c0f, const float* __restrict__ c0b) {
    int idx = blockIdx.x * blockDim.x + threadIdx.x;   // B*U = 32768
    if (idx == 0) g_sc = 0;
    int u = idx & (UU - 1);
    g_hFa[idx] = tanhf(c0f[u]);
    g_hBa[idx] = tanhf(c0b[u]);
}

// ---------------- big GEMM: C = AT^T @ B, cp.async double-buffered ------------
__global__ void __launch_bounds__(256) sgemm_nt(
    const float* __restrict__ AT, const float* __restrict__ B, float* __restrict__ C,
    int K, int ldat, int ldb, int ldc) {
    __shared__ float As[2][16 * 132];
    __shared__ float Bs[2][16 * 132];
    int m0 = blockIdx.y * 128, n0 = blockIdx.x * 128;
    int tid = threadIdx.x;
    int tx = tid & 15, ty = tid >> 4;
    uint32_t as0 = (uint32_t)__cvta_generic_to_shared(&As[0][0]);
    uint32_t bs0 = (uint32_t)__cvta_generic_to_shared(&Bs[0][0]);
    int akk = tid >> 5, aoff = (tid & 31) * 4;

    ull acc[4][8];
#pragma unroll
    for (int p = 0; p < 4; p++)
#pragma unroll
        for (int j = 0; j < 8; j++) acc[p][j] = 0ULL;

#define SG_STAGE(pp, kk0) do { \
        cp_async16(as0 + (uint32_t)(((pp) * 2112 + akk * 132 + aoff) * 4), \
                   AT + (size_t)((kk0) + akk) * ldat + m0 + aoff); \
        cp_async16(as0 + (uint32_t)(((pp) * 2112 + (akk + 8) * 132 + aoff) * 4), \
                   AT + (size_t)((kk0) + akk + 8) * ldat + m0 + aoff); \
        cp_async16(bs0 + (uint32_t)(((pp) * 2112 + akk * 132 + aoff) * 4), \
                   B + (size_t)((kk0) + akk) * ldb + n0 + aoff); \
        cp_async16(bs0 + (uint32_t)(((pp) * 2112 + (akk + 8) * 132 + aoff) * 4), \
                   B + (size_t)((kk0) + akk + 8) * ldb + n0 + aoff); \
    } while (0)

    SG_STAGE(0, 0);
    cp_commit();

    int p = 0;
    for (int k0 = 0; k0 < K; k0 += 16, p ^= 1) {
        if (k0 + 16 < K) {
            SG_STAGE(p ^ 1, k0 + 16);
            cp_commit();
            cp_wait<1>();
        } else {
            cp_wait<0>();
        }
        __syncthreads();
        const float* Ap = &As[p][0];
        const float* Bp = &Bs[p][0];
#pragma unroll
        for (int kk = 0; kk < 16; kk++) {
            ull ap[4];
#pragma unroll
            for (int q = 0; q < 4; q++)
                ap[q] = *(const ull*)(Ap + kk * 132 + ty * 8 + 2 * q);
            float4 bv0 = *(const float4*)(Bp + kk * 132 + tx * 8);
            float4 bv1 = *(const float4*)(Bp + kk * 132 + tx * 8 + 4);
            ull bd[8] = {dup2(bv0.x), dup2(bv0.y), dup2(bv0.z), dup2(bv0.w),
                         dup2(bv1.x), dup2(bv1.y), dup2(bv1.z), dup2(bv1.w)};
#pragma unroll
            for (int q = 0; q < 4; q++)
#pragma unroll
                for (int j = 0; j < 8; j++) fma2(acc[q][j], ap[q], bd[j]);
        }
        __syncthreads();
    }
#undef SG_STAGE

#pragma unroll
    for (int q = 0; q < 4; q++) {
        float v0[8], v1[8];
#pragma unroll
        for (int j = 0; j < 8; j++) {
            float2 t = unpack2(acc[q][j]);
            v0[j] = t.x; v1[j] = t.y;
        }
        float* c0 = C + (size_t)(m0 + ty * 8 + 2 * q) * ldc + n0 + tx * 8;
        float* c1 = c0 + ldc;
        *(float4*)c0 = make_float4(v0[0], v0[1], v0[2], v0[3]);
        *(float4*)(c0 + 4) = make_float4(v0[4], v0[5], v0[6], v0[7]);
        *(float4*)c1 = make_float4(v1[0], v1[1], v1[2], v1[3]);
        *(float4*)(c1 + 4) = make_float4(v1[4], v1[5], v1[6], v1[7]);
    }
}

// ---------------- fused recurrence layer: 128 CTAs x 128 thr, 1 launch --------
// blk>>6 = dir, blk&63 = 32-wide gate tile. Thread tile 4b x 4g (R9 geometry).
// W slice RESIDENT in smem (64KB, loaded once); A staged per step via 4-stage
// cp.async.cg ring; c in registers; h exchanged via global + fenced barrier.
__global__ void __launch_bounds__(128) lstm_layer(
    const float* __restrict__ preF, const float* __restrict__ preB,
    const float* __restrict__ WpF,  const float* __restrict__ WpB,
    const float* __restrict__ bvF,  const float* __restrict__ bvB,
    const float* __restrict__ c0F,  const float* __restrict__ c0B,
    float* __restrict__ outF, float* __restrict__ outB,
    float* __restrict__ outTF, float* __restrict__ outTB, int ostride) {
    extern __shared__ float sm[];
    float* Wsm = sm;                    // 16384 floats (resident W slice)
    float* Asm = sm + 16384;            // 4 stages x 2304 floats

    int blk = blockIdx.x;
    int dir = blk >> 6;
    int nb  = blk & 63;
    int n0  = nb * 32;

    const float* pre = dir ? preB : preF;
    const float* Wp  = dir ? WpB : WpF;
    const float* bv  = dir ? bvB : bvF;
    const float* c0p = dir ? c0B : c0F;
    float* outp  = dir ? outB : outF;
    float* outT  = dir ? outTB : outTF;
    float* hbuf0 = dir ? g_hBa : g_hFa;
    float* hbuf1 = dir ? g_hBb : g_hFb;

    int tid = threadIdx.x;
    int tx = tid >> 4;            // 0..7 : unit within tile
    int ty = tid & 15;            // 0..15: b-group of 4
    int b0 = ty * 4;
    int u = nb * 8 + tx;

    uint32_t wsb = (uint32_t)__cvta_generic_to_shared(Wsm);
    uint32_t asb = (uint32_t)__cvta_generic_to_shared(Asm);

    // load resident W slice: 16384 floats; each thread fills its contiguous
    // 128-float span with 32 x 16B cp.asyncs.  (R10/R11 bug: stride was 16
    // floats per 16-BYTE copy, leaving 3/4 of Wsm uninitialized.)
#pragma unroll
    for (int j = 0; j < 32; j++) {
        int f = tid * 128 + j * 4;
        int row = f >> 6, col = f & 63;
        cp_async16(wsb + (uint32_t)f * 4, Wp + (size_t)row * 4096 + nb * 64 + col);
    }
    cp_commit();

    float4 bb4 = *(const float4*)(bv + n0 + tx * 4);
    float c0v = c0p[u];
    float cv[4] = {c0v, c0v, c0v, c0v};

    // A staging assignment (R9 layout): permuted rows, stride 36
    int sa_row = tid >> 1, sa_off = (tid & 1) * 16;
    int sa_prow = (sa_row & 3) * 16 + (sa_row >> 2);

    cp_wait<0>();
    __syncthreads();   // W resident ready

#define LSA(st, k0) do { \
        _Pragma("unroll") \
        for (int j = 0; j < 4; j++) \
            cp_async16(asb + (uint32_t)((((st) * 2304) + sa_prow * 36 + sa_off + j * 4) * 4), \
                       hin + sa_row * UU + (k0) + sa_off + j * 4); \
    } while (0)

    for (int s = 0; s < T_LEN; s++) {
        int t = dir ? (T_LEN - 1 - s) : s;
        const float* hin = (s & 1) ? hbuf1 : hbuf0;
        float* hout      = (s & 1) ? hbuf0 : hbuf1;

        // per-step pre loads (latency hides under staging + k-loop)
        float4 pv[4];
#pragma unroll
        for (int r = 0; r < 4; r++)
            pv[r] = *(const float4*)(pre + ((size_t)t * BB + b0 + r) * G4 + n0 + tx * 4);

        LSA(0, 0);  cp_commit();
        LSA(1, 32); cp_commit();
        LSA(2, 64); cp_commit();

        ull acc[4][4];
#pragma unroll
        for (int r = 0; r < 4; r++)
#pragma unroll
            for (int j = 0; j < 4; j++) acc[r][j] = 0ULL;

        for (int i = 0; i < 16; i++) {
            if (i < 13)      cp_wait<2>();
            else if (i < 15) cp_wait<1>();
            else             cp_wait<0>();
            __syncthreads();
            const float* Ap = Asm + (i & 3) * 2304;
            const float* Bp = Wsm + i * 1024;
#pragma unroll
            for (int kk4 = 0; kk4 < 8; kk4++) {
                ulonglong2 a2[4];
#pragma unroll
                for (int r = 0; r < 4; r++)
                    a2[r] = *(const ulonglong2*)(Ap + (r * 16 + ty) * 36 + kk4 * 4);
#pragma unroll
                for (int h = 0; h < 2; h++) {
                    int kk2 = kk4 * 2 + h;
                    ulonglong2 w01 = *(const ulonglong2*)(Bp + kk2 * 64 + tx * 4);
                    ulonglong2 w23 = *(const ulonglong2*)(Bp + kk2 * 64 + 32 + tx * 4);
#pragma unroll
                    for (int r = 0; r < 4; r++) {
                        ull a = h ? a2[r].y : a2[r].x;
                        fma2(acc[r][0], a, w01.x);
                        fma2(acc[r][1], a, w01.y);
                        fma2(acc[r][2], a, w23.x);
                        fma2(acc[r][3], a, w23.y);
                    }
                }
            }
            if (i + 3 < 16) { LSA((i + 3) & 3, (i + 3) * 32); cp_commit(); }
        }

        // epilogue: gates + state update (c stays in registers)
#pragma unroll
        for (int r = 0; r < 4; r++) {
            int b = b0 + r;
            float2 e0 = unpack2(acc[r][0]);
            float2 e1 = unpack2(acc[r][1]);
            float2 e2 = unpack2(acc[r][2]);
            float2 e3 = unpack2(acc[r][3]);
            float gi = e0.x + e0.y + pv[r].x + bb4.x;
            float gf = e1.x + e1.y + pv[r].y + bb4.y;
            float go = e2.x + e2.y + pv[r].z + bb4.z;
            float gg = e3.x + e3.y + pv[r].w + bb4.w;
            float ig = 1.f / (1.f + expf(-gi));
            float fg = 1.f / (1.f + expf(-gf));
            float og = 1.f / (1.f + expf(-go));
            float gt = tanhf(gg);
            float c = fg * cv[r] + ig * gt;
            float h = og * tanhf(c);
            cv[r] = c;
            hout[b * UU + u] = h;
            outp[((size_t)t * BB + b) * ostride + u] = h;
            if (outT) outT[(size_t)u * MTOT + t * BB + b] = h;
        }

        if (s + 1 < T_LEN) gbar((unsigned)(NCTA * (s + 1)));
    }
#undef LSA
}

// ---------------- span feature gather ----------------------------------------
__global__ void build_hi(const int* __restrict__ sl, const int* __restrict__ sr,
                         const int* __restrict__ ll, const int* __restrict__ lr) {
    int idx = blockIdx.x * blockDim.x + threadIdx.x;
    const int NS = BB * 4 * 2048;
    int b, s, c, le, ri;
    float* dst;
    if (idx < NS) {
        b = idx / (4 * 2048); int r = idx - b * (4 * 2048);
        s = r / 2048; c = r - s * 2048;
        le = sl[b * 4 + s]; ri = sr[b * 4 + s];
        dst = g_hi_s + (size_t)b * 8192 + s * 2048 + c;
    } else {
        int j = idx - NS;
        b = j / (3 * 2048); int r = j - b * (3 * 2048);
        s = r / 2048; c = r - s * 2048;
        le = ll[b * 3 + s]; ri = lr[b * 3 + s];
        dst = g_hi_l + (size_t)b * 6144 + s * 2048 + c;
    }
    float v;
    if (c < 512) {
        v = g_in2[((size_t)ri * BB + b) * 1024 + c] - g_in2[((size_t)(le - 1) * BB + b) * 1024 + c];
    } else if (c < 1024) {
        int u = c - 512;
        v = g_fwd2[((size_t)ri * BB + b) * UU + u] - g_fwd2[((size_t)(le - 1) * BB + b) * UU + u];
    } else if (c < 1536) {
        int u = c - 1024;
        v = g_in2[((size_t)le * BB + b) * 1024 + 512 + u] - g_in2[((size_t)(ri + 1) * BB + b) * 1024 + 512 + u];
    } else {
        int u = c - 1536;
        v = g_back2[((size_t)le * BB + b) * UU + u] - g_back2[((size_t)(ri + 1) * BB + b) * UU + u];
    }
    *dst = v;
}

// ---------------- span hidden GEMM: M=64, split-K -----------------------------
__global__ void __launch_bounds__(256) span_gemm(
    const float* __restrict__ A, int lda, const float* __restrict__ B,
    float* __restrict__ Cpart) {
    __shared__ float AsT[16][68];
    __shared__ float Bs[16][68];
    int n0 = blockIdx.x * 64;
    int kbase = blockIdx.y * 512;
    int tid = threadIdx.x;
    int tx = tid & 15, ty = tid >> 4;
    float acc[4][4] = {{0}};
    int ab = tid >> 2, aseg = (tid & 3) * 4;
    int bkk = tid >> 4, bnn = (tid & 15) * 4;
    for (int k0 = kbase; k0 < kbase + 512; k0 += 16) {
        float4 av = *(const float4*)(A + (size_t)ab * lda + k0 + aseg);
        float4 wv = *(const float4*)(B + (size_t)(k0 + bkk) * HD + n0 + bnn);
        __syncthreads();
        AsT[aseg + 0][ab] = av.x; AsT[aseg + 1][ab] = av.y;
        AsT[aseg + 2][ab] = av.z; AsT[aseg + 3][ab] = av.w;
        *(float4*)&Bs[bkk][bnn] = wv;
        __syncthreads();
#pragma unroll
        for (int kk = 0; kk < 16; kk++) {
            float4 a = *(float4*)&AsT[kk][ty * 4];
            float4 w = *(float4*)&Bs[kk][tx * 4];
            float aa[4] = {a.x, a.y, a.z, a.w};
            float ww[4] = {w.x, w.y, w.z, w.w};
#pragma unroll
            for (int i = 0; i < 4; i++)
#pragma unroll
                for (int j = 0; j < 4; j++) acc[i][j] += aa[i] * ww[j];
        }
    }
#pragma unroll
    for (int i = 0; i < 4; i++) {
        int b = ty * 4 + i;
        float4 v = {acc[i][0], acc[i][1], acc[i][2], acc[i][3]};
        *(float4*)(Cpart + ((size_t)blockIdx.y * BB + b) * HD + n0 + tx * 4) = v;
    }
}

__global__ void reduce_relu(const float* __restrict__ part, int nch,
                            const float* __restrict__ bias, float* __restrict__ outh) {
    int idx = blockIdx.x * blockDim.x + threadIdx.x;
    int n = idx & (HD - 1);
    float s = bias[n];
    for (int ch = 0; ch < nch; ch++) s += part[(size_t)ch * BB * HD + idx];
    outh[idx] = fmaxf(s, 0.f);
}

// ---------------- output heads ------------------------------------------------
__global__ void out_heads(const float* __restrict__ soW, const float* __restrict__ sob,
                          const float* __restrict__ loW, const float* __restrict__ lob,
                          float* __restrict__ out) {
    __shared__ float s1[HD], s2[HD];
    int b = blockIdx.x, tid = threadIdx.x;
    for (int i = tid; i < HD; i += blockDim.x) {
        s1[i] = g_hs[b * HD + i];
        s2[i] = g_hl[b * HD + i];
    }
    __syncthreads();
    if (tid < 2) {
        float s = sob[tid];
        for (int k = 0; k < HD; k++) s += s1[k] * soW[k * 2 + tid];
        out[b * 2 + tid] = s;
    } else if (tid < 34) {
        int j = tid - 2;
        float s = lob[j];
        for (int k = 0; k < HD; k++) s += s2[k] * loW[k * 32 + j];
        out[128 + b * 32 + j] = s;
    }
}

// ---------------- host driver --------------------------------------------------
static float* sym(const void* symbol) {
    void* p = nullptr;
    cudaGetSymbolAddress(&p, symbol);
    return (float*)p;
}

extern "C" void kernel_launch(void* const* d_in, const int* in_sizes, int n_in,
                              void* d_out, int out_size) {
    const float* word_emb = (const float*)d_in[0];
    const float* tag_emb  = (const float*)d_in[1];
    const float* l1f_W = (const float*)d_in[2];
    const float* l1f_b = (const float*)d_in[3];
    const float* l1f_c0 = (const float*)d_in[4];
    const float* l1b_W = (const float*)d_in[5];
    const float* l1b_b = (const float*)d_in[6];
    const float* l1b_c0 = (const float*)d_in[7];
    const float* l2f_W = (const float*)d_in[8];
    const float* l2f_b = (const float*)d_in[9];
    const float* l2f_c0 = (const float*)d_in[10];
    const float* l2b_W = (const float*)d_in[11];
    const float* l2b_b = (const float*)d_in[12];
    const float* l2b_c0 = (const float*)d_in[13];
    const float* sh_W = (const float*)d_in[14];
    const float* sh_b = (const float*)d_in[15];
    const float* so_W = (const float*)d_in[16];
    const float* so_b = (const float*)d_in[17];
    const float* lh_W = (const float*)d_in[18];
    const float* lh_b = (const float*)d_in[19];
    const float* lo_W = (const float*)d_in[20];
    const float* lo_b = (const float*)d_in[21];
    const int* word_inds = (const int*)d_in[22];
    const int* tag_inds  = (const int*)d_in[23];
    const int* s_lefts  = (const int*)d_in[24];
    const int* s_rights = (const int*)d_in[25];
    const int* l_lefts  = (const int*)d_in[26];
    const int* l_rights = (const int*)d_in[27];
    float* out = (float*)d_out;

    float* p_sent  = sym(g_sent);
    float* p_sentT = sym(g_sentT);
    float* p_preF  = sym(g_preF);
    float* p_preB  = sym(g_preB);
    float* p_in2   = sym(g_in2);
    float* p_in2T  = sym(g_in2T);
    float* p_fwd2  = sym(g_fwd2);
    float* p_back2 = sym(g_back2);
    float* p_Wx1f = sym(g_Wx1f); float* p_Wx1b = sym(g_Wx1b);
    float* p_Wh1f = sym(g_Wh1f); float* p_Wh1b = sym(g_Wh1b);
    float* p_Wx2f = sym(g_Wx2f); float* p_Wx2b = sym(g_Wx2b);
    float* p_Wh2f = sym(g_Wh2f); float* p_Wh2b = sym(g_Wh2b);
    float* p_bv1f = sym(g_bv1f); float* p_bv1b = sym(g_bv1b);
    float* p_bv2f = sym(g_bv2f); float* p_bv2b = sym(g_bv2b);
    float* p_hi_s = sym(g_hi_s); float* p_hi_l = sym(g_hi_l);
    float* p_part_s = sym(g_part_s); float* p_part_l = sym(g_part_l);
    float* p_hs = sym(g_hs); float* p_hl = sym(g_hl);

    const int LSTM_SMEM = (16384 + 4 * 2304) * 4;   // 102,400 B
    static int smem_set = 0;
    if (!smem_set) {
        cudaFuncSetAttribute(lstm_layer, cudaFuncAttributeMaxDynamicSharedMemorySize,
                             LSTM_SMEM);
        smem_set = 1;
    }

    // 1) pack weights
    pack_lstm<<<2048, 256>>>(l1f_W, l1f_b, p_Wx1f, p_Wh1f, p_bv1f, SENT_D);
    pack_lstm<<<2048, 256>>>(l1b_W, l1b_b, p_Wx1b, p_Wh1b, p_bv1b, SENT_D);
    pack_lstm<<<4096, 256>>>(l2f_W, l2f_b, p_Wx2f, p_Wh2f, p_bv2f, 1024);
    pack_lstm<<<4096, 256>>>(l2b_W, l2b_b, p_Wx2b, p_Wh2b, p_bv2b, 1024);

    // 2) embeddings + transpose for GEMM A operand
    embed_kernel<<<(MTOT * SENT_D) / 256, 256>>>(word_emb, tag_emb, word_inds, tag_inds);
    transpose32<<<dim3(SENT_D / 32, MTOT / 32), dim3(32, 8)>>>(p_sent, p_sentT, MTOT, SENT_D);

    // 3) layer-1 input projections (16384 x 320 x 2048)
    dim3 gpre(G4 / 128, MTOT / 128);
    sgemm_nt<<<gpre, 256>>>(p_sentT, p_Wx1f, p_preF, SENT_D, MTOT, G4, G4);
    sgemm_nt<<<gpre, 256>>>(p_sentT, p_Wx1b, p_preB, SENT_D, MTOT, G4, G4);

    // 4) layer-1 recurrence: ONE fused persistent launch
    init_states<<<(BB * UU) / 256, 256>>>(l1f_c0, l1b_c0);
    lstm_layer<<<NCTA, 128, LSTM_SMEM>>>(
        p_preF, p_preB, p_Wh1f, p_Wh1b, p_bv1f, p_bv1b, l1f_c0, l1b_c0,
        p_in2, p_in2 + 512, p_in2T, p_in2T + (size_t)512 * MTOT, 1024);

    // 5) layer-2 input projections (16384 x 1024 x 2048)
    sgemm_nt<<<gpre, 256>>>(p_in2T, p_Wx2f, p_preF, 1024, MTOT, G4, G4);
    sgemm_nt<<<gpre, 256>>>(p_in2T, p_Wx2b, p_preB, 1024, MTOT, G4, G4);

    // 6) layer-2 recurrence
    init_states<<<(BB * UU) / 256, 256>>>(l2f_c0, l2b_c0);
    lstm_layer<<<NCTA, 128, LSTM_SMEM>>>(
        p_preF, p_preB, p_Wh2f, p_Wh2b, p_bv2f, p_bv2b, l2f_c0, l2b_c0,
        p_fwd2, p_back2, (float*)nullptr, (float*)nullptr, UU);

    // 7) span features
    build_hi<<<(BB * 7 * 2048) / 256, 256>>>(s_lefts, s_rights, l_lefts, l_rights);

    // 8) span hidden layers
    span_gemm<<<dim3(HD / 64, 16), 256>>>(p_hi_s, 8192, sh_W, p_part_s);
    span_gemm<<<dim3(HD / 64, 12), 256>>>(p_hi_l, 6144, lh_W, p_part_l);
    reduce_relu<<<(BB * HD) / 256, 256>>>(p_part_s, 16, sh_b, p_hs);
    reduce_relu<<<(BB * HD) / 256, 256>>>(p_part_l, 12, lh_b, p_hl);

    // 9) output heads
    out_heads<<<BB, 128>>>(so_W, so_b, lo_W, lo_b, out);
}